// round 6
// baseline (speedup 1.0000x reference)
#include <cuda_runtime.h>
#include <math.h>
#include <stdint.h>

// ---------------------------------------------------------------------------
// Problem constants
// ---------------------------------------------------------------------------
static constexpr int B_   = 128;
static constexpr int C_   = 2048;   // C_ENC
static constexpr int HW   = 49;     // H*W
static constexpr int FIN  = 512;    // F_IN
static constexpr int G_   = 8;      // F_HID
static constexpr int NP   = 192;    // N_PTS (== N_CONVGRID)
static constexpr int S2   = 49;     // (LMAX+1)^2
static constexpr int SO3  = 455;    // sum (2l+1)^2
static constexpr int NG   = 4000;   // N_SO3GRID
static constexpr int GI   = G_ * S2;   // 392
static constexpr int SPLITK = 8;

static constexpr float RS192 = 0.07216878364870323f;  // 1/sqrt(192)
static constexpr float RS512 = 0.04419417382415922f;  // 1/sqrt(512)

// ---------------------------------------------------------------------------
// Scratch (device globals; runtime allocation is forbidden)
// ---------------------------------------------------------------------------
__device__ float d_P[HW * S2];            // 49x49
__device__ float d_q[S2];                 // col sums of P
__device__ float d_psi[FIN * GI];         // [f][g][i]
__device__ float d_bpsi[GI];              // [g][i]
__device__ float d_psi2[G_ * SO3];        // [f][i]
__device__ float d_W2[C_ * GI];           // [c][g*49+i]
__device__ float d_fmapP[(size_t)B_ * C_ * S2];      // 51.4 MB
__device__ float d_x4[B_ * G_ * SO3];     // [b][g][455]
__device__ float d_gact[(size_t)B_ * G_ * NG];       // 16.4 MB
__device__ float d_part[(size_t)SPLITK * B_ * G_ * SO3];
__device__ float d_x5[B_ * G_ * SO3];

__constant__ int c_off2[8] = {0, 1, 10, 35, 84, 165, 286, 455};

// ---------------------------------------------------------------------------
// Small precompute kernels
// ---------------------------------------------------------------------------

// P[hw][i] = (1/sqrt192) * sum_n proj_w[hw][n] * proj_Y[n][i];  q[i] = sum_hw P
__global__ void k_P(const float* __restrict__ proj_w, const float* __restrict__ proj_Y) {
    __shared__ float sP[HW * S2];
    const int tid = threadIdx.x;
    for (int idx = tid; idx < HW * S2; idx += blockDim.x) {
        int hw = idx / S2, i = idx % S2;
        const float* wr = proj_w + hw * NP;
        float acc = 0.f;
        #pragma unroll 4
        for (int n = 0; n < NP; n++) acc += wr[n] * proj_Y[n * S2 + i];
        acc *= RS192;
        sP[idx] = acc;
        d_P[idx] = acc;
    }
    __syncthreads();
    for (int i = tid; i < S2; i += blockDim.x) {
        float acc = 0.f;
        for (int hw = 0; hw < HW; hw++) acc += sP[hw * S2 + i];
        d_q[i] = acc;
    }
}

// psi[f][g][i] = (1/sqrt192) * sum_n fs_w[f][g][n] * fs_Y[n][i]
__global__ void k_psi(const float* __restrict__ fs_w, const float* __restrict__ fs_Y) {
    int t = blockIdx.x * blockDim.x + threadIdx.x;
    if (t >= FIN * GI) return;
    int i = t % S2;
    int fg = t / S2;
    const float* wr = fs_w + (size_t)fg * NP;
    float acc = 0.f;
    #pragma unroll 4
    for (int n = 0; n < NP; n++) acc += wr[n] * fs_Y[n * S2 + i];
    d_psi[t] = acc * RS192;
}

// bpsi[g][i] = (1/sqrt512) * sum_f conv_b[f] * psi[f][g][i]
__global__ void k_bpsi(const float* __restrict__ conv_b) {
    int t = blockIdx.x * blockDim.x + threadIdx.x;
    if (t >= GI) return;
    float acc = 0.f;
    for (int f = 0; f < FIN; f++) acc += conv_b[f] * d_psi[f * GI + t];
    d_bpsi[t] = acc * RS512;
}

// psi2[f][i] = (1/sqrt192) * sum_n so3_w[f][0][n] * so3_D[n][i]
__global__ void k_psi2(const float* __restrict__ so3_w, const float* __restrict__ so3_D) {
    int t = blockIdx.x * blockDim.x + threadIdx.x;
    if (t >= G_ * SO3) return;
    int f = t / SO3, i = t % SO3;
    const float* wr = so3_w + f * NP;
    float acc = 0.f;
    #pragma unroll 4
    for (int n = 0; n < NP; n++) acc += wr[n] * so3_D[n * SO3 + i];
    d_psi2[t] = acc * RS192;
}

// ---------------------------------------------------------------------------
// Generic register-tiled fp32 GEMM:  C = alpha * A @ B
// A: [M,K] row-major (ATRANS=false)  or  [K,M] row-major (ATRANS=true)
// B: [K,N] row-major.  blockIdx.z = split-K slab (writes C + z*M*N).
// ---------------------------------------------------------------------------
template<int BM, int BN, int BK, int TM, int TN, bool ATRANS, bool RELU>
__global__ void sgemm_kernel(const float* __restrict__ A, const float* __restrict__ Bm,
                             float* __restrict__ C, int M, int N, int K,
                             float alpha, int kChunk) {
    constexpr int TX = BN / TN;
    constexpr int TY = BM / TM;
    constexpr int THREADS = TX * TY;
    __shared__ float As[BK][BM];
    __shared__ float Bs[BK][BN];
    const int tid = threadIdx.x;
    const int tx = tid % TX;
    const int ty = tid / TX;
    const int rowBase = blockIdx.y * BM;
    const int colBase = blockIdx.x * BN;
    const int k0 = blockIdx.z * kChunk;
    const int kEnd = min(K, k0 + kChunk);

    float acc[TM][TN];
    #pragma unroll
    for (int i = 0; i < TM; i++)
        #pragma unroll
        for (int j = 0; j < TN; j++) acc[i][j] = 0.f;

    for (int kt = k0; kt < kEnd; kt += BK) {
        if (ATRANS) {
            #pragma unroll
            for (int idx = tid; idx < BK * BM; idx += THREADS) {
                int kk = idx / BM, m = idx % BM;
                int gk = kt + kk, gm = rowBase + m;
                As[kk][m] = (gk < kEnd && gm < M) ? A[(size_t)gk * M + gm] : 0.f;
            }
        } else {
            #pragma unroll
            for (int idx = tid; idx < BM * BK; idx += THREADS) {
                int m = idx / BK, kk = idx % BK;
                int gm = rowBase + m, gk = kt + kk;
                As[kk][m] = (gk < kEnd && gm < M) ? A[(size_t)gm * K + gk] : 0.f;
            }
        }
        #pragma unroll
        for (int idx = tid; idx < BK * BN; idx += THREADS) {
            int kk = idx / BN, n = idx % BN;
            int gk = kt + kk, gn = colBase + n;
            Bs[kk][n] = (gk < kEnd && gn < N) ? Bm[(size_t)gk * N + gn] : 0.f;
        }
        __syncthreads();
        #pragma unroll
        for (int kk = 0; kk < BK; kk++) {
            float a[TM], bb[TN];
            #pragma unroll
            for (int i = 0; i < TM; i++) a[i] = As[kk][ty * TM + i];
            #pragma unroll
            for (int j = 0; j < TN; j++) bb[j] = Bs[kk][tx * TN + j];
            #pragma unroll
            for (int i = 0; i < TM; i++)
                #pragma unroll
                for (int j = 0; j < TN; j++) acc[i][j] += a[i] * bb[j];
        }
        __syncthreads();
    }

    float* Co = C + (size_t)blockIdx.z * M * N;
    #pragma unroll
    for (int i = 0; i < TM; i++) {
        int gm = rowBase + ty * TM + i;
        if (gm >= M) continue;
        #pragma unroll
        for (int j = 0; j < TN; j++) {
            int gn = colBase + tx * TN + j;
            if (gn >= N) continue;
            float v = alpha * acc[i][j];
            if (RELU) v = fmaxf(v, 0.f);
            Co[(size_t)gm * N + gn] = v;
        }
    }
}

// ---------------------------------------------------------------------------
// Stage D: per-l block GEMM.  out[b,g,u,m] = sum_c fmapP[b,c,s+m]*W2[c,g,s+u]
// (W2 already carries 1/sqrt512). grid = (128 b, 7 l), 128 threads.
// Thread computes a 4x4 (u,m) microtile for one g.
// ---------------------------------------------------------------------------
static constexpr int KC = 32;
__global__ void stageD_kernel() {
    const int b = blockIdx.x;
    const int l = blockIdx.y;
    const int d = 2 * l + 1;
    const int s = l * l;
    const int off2 = c_off2[l];
    const int nt = (d + 3) >> 2;        // u/m tiles of 4
    const int tpg = nt * nt;
    const int tid = threadIdx.x;
    const bool active = tid < 8 * tpg;
    int g = 0, ut = 0, mt = 0;
    if (active) { g = tid / tpg; int r = tid % tpg; ut = r / nt; mt = r % nt; }

    __shared__ float Af[KC][16];     // [cc][m]
    __shared__ float Bw[KC][128];    // [cc][g*16+u]

    float acc[4][4];
    #pragma unroll
    for (int i = 0; i < 4; i++)
        #pragma unroll
        for (int j = 0; j < 4; j++) acc[i][j] = 0.f;

    const float* fm = d_fmapP + (size_t)b * C_ * S2;

    for (int c0 = 0; c0 < C_; c0 += KC) {
        #pragma unroll
        for (int idx = tid; idx < KC * 16; idx += 128) {
            int cc = idx >> 4, m = idx & 15;
            Af[cc][m] = (m < d) ? fm[(size_t)(c0 + cc) * S2 + s + m] : 0.f;
        }
        #pragma unroll
        for (int idx = tid; idx < KC * 128; idx += 128) {
            int cc = idx >> 7, r = idx & 127;
            int gg = r >> 4, u = r & 15;
            Bw[cc][r] = (u < d) ? d_W2[(size_t)(c0 + cc) * GI + gg * S2 + s + u] : 0.f;
        }
        __syncthreads();
        if (active) {
            #pragma unroll 8
            for (int cc = 0; cc < KC; cc++) {
                float a[4], bb[4];
                #pragma unroll
                for (int j = 0; j < 4; j++) a[j] = Af[cc][mt * 4 + j];
                #pragma unroll
                for (int i = 0; i < 4; i++) bb[i] = Bw[cc][g * 16 + ut * 4 + i];
                #pragma unroll
                for (int i = 0; i < 4; i++)
                    #pragma unroll
                    for (int j = 0; j < 4; j++) acc[i][j] += bb[i] * a[j];
            }
        }
        __syncthreads();
    }

    if (active) {
        #pragma unroll
        for (int i = 0; i < 4; i++) {
            int u = ut * 4 + i;
            if (u >= d) continue;
            #pragma unroll
            for (int j = 0; j < 4; j++) {
                int m = mt * 4 + j;
                if (m >= d) continue;
                float v = acc[i][j] + d_bpsi[g * S2 + s + u] * d_q[s + m];
                d_x4[(size_t)(b * G_ + g) * SO3 + off2 + u * d + m] = v;
            }
        }
    }
}

// reduce split-K partials:  x5 = sum_z part[z]
__global__ void k_reduce() {
    int t = blockIdx.x * blockDim.x + threadIdx.x;
    const int MN = B_ * G_ * SO3;
    if (t >= MN) return;
    float s = 0.f;
    #pragma unroll
    for (int z = 0; z < SPLITK; z++) s += d_part[(size_t)z * MN + t];
    d_x5[t] = s;
}

// Stage H: so3->so3 conv, F_HID=8 -> 1 channel.
// out[b, off2 + v*d + m] = (1/sqrt(8d)) * sum_{f,u} x5[b,f,off2+u*d+m]*psi2[f,off2+u*d+v]
__global__ void stageH_kernel(float* __restrict__ out) {
    int t = blockIdx.x * blockDim.x + threadIdx.x;
    if (t >= B_ * SO3) return;
    int b = t / SO3, j = t % SO3;
    int l = 6;
    while (j < c_off2[l]) l--;
    int d = 2 * l + 1;
    int r = j - c_off2[l];
    int v = r / d, m = r % d;
    float acc = 0.f;
    #pragma unroll
    for (int f = 0; f < G_; f++) {
        const float* xr = d_x5 + (size_t)(b * G_ + f) * SO3 + c_off2[l];
        const float* pr = d_psi2 + f * SO3 + c_off2[l];
        for (int u = 0; u < d; u++) acc += xr[u * d + m] * pr[u * d + v];
    }
    out[t] = acc * (1.0f / sqrtf(8.0f * d));
}

// ---------------------------------------------------------------------------
// Host launcher
// ---------------------------------------------------------------------------
extern "C" void kernel_launch(void* const* d_in, const int* in_sizes, int n_in,
                              void* d_out, int out_size) {
    const float* fmap     = (const float*)d_in[0];   // [128,2048,7,7]
    const float* conv_w   = (const float*)d_in[1];   // [512,2048]
    const float* conv_b   = (const float*)d_in[2];   // [512]
    const float* proj_w   = (const float*)d_in[3];   // [7,7,192]
    const float* proj_Y   = (const float*)d_in[4];   // [192,49]
    const float* fs_w     = (const float*)d_in[5];   // [512,8,192]
    const float* fs_Y     = (const float*)d_in[6];   // [192,49]
    const float* act_to   = (const float*)d_in[7];   // [455,4000]
    const float* act_from = (const float*)d_in[8];   // [4000,455]
    const float* so3_w    = (const float*)d_in[9];   // [8,1,192]
    const float* so3_D    = (const float*)d_in[10];  // [192,455]
    float* out = (float*)d_out;                      // [128,1,455]

    // symbol addresses (host API, capture-safe: no stream work, no allocs)
    float *pP, *pPsi, *pW2, *pFmapP, *pX4, *pGact, *pPart, *pX5;
    cudaGetSymbolAddress((void**)&pP,     d_P);
    cudaGetSymbolAddress((void**)&pPsi,   d_psi);
    cudaGetSymbolAddress((void**)&pW2,    d_W2);
    cudaGetSymbolAddress((void**)&pFmapP, d_fmapP);
    cudaGetSymbolAddress((void**)&pX4,    d_x4);
    cudaGetSymbolAddress((void**)&pGact,  d_gact);
    cudaGetSymbolAddress((void**)&pPart,  d_part);
    cudaGetSymbolAddress((void**)&pX5,    d_x5);

    // 1) small precomputes
    k_P<<<1, 256>>>(proj_w, proj_Y);
    k_psi<<<(FIN * GI + 255) / 256, 256>>>(fs_w, fs_Y);
    k_bpsi<<<(GI + 255) / 256, 256>>>(conv_b);
    k_psi2<<<(G_ * SO3 + 255) / 256, 256>>>(so3_w, so3_D);

    // 2) W2[c, g*49+i] = (1/sqrt512) conv_w^T @ psi    (M=2048, N=392, K=512)
    sgemm_kernel<64, 64, 8, 4, 4, true, false>
        <<<dim3(7, 32, 1), 256>>>(conv_w, pPsi, pW2, C_, GI, FIN, RS512, FIN);

    // 3) fmapP = fmap(rows=b*c) @ P                    (M=262144, N=49, K=49)
    sgemm_kernel<128, 64, 8, 8, 4, false, false>
        <<<dim3(1, (B_ * C_) / 128, 1), 256>>>(fmap, pP, pFmapP,
                                               B_ * C_, S2, HW, 1.0f, HW);

    // 4) s2->so3 block GEMMs + bias -> x4
    stageD_kernel<<<dim3(B_, 7), 128>>>();

    // 5) g = relu(x4 @ act_to)                          (M=1024, N=4000, K=455)
    sgemm_kernel<128, 128, 8, 8, 8, false, true>
        <<<dim3((NG + 127) / 128, (B_ * G_) / 128, 1), 256>>>(
            pX4, act_to, pGact, B_ * G_, NG, SO3, 1.0f, SO3);

    // 6) x5 = g @ act_from (split-K=8 for SM occupancy) (M=1024, N=455, K=4000)
    sgemm_kernel<128, 128, 8, 8, 8, false, false>
        <<<dim3((SO3 + 127) / 128, (B_ * G_) / 128, SPLITK), 256>>>(
            pGact, act_from, pPart, B_ * G_, SO3, NG, 1.0f, NG / SPLITK);
    k_reduce<<<(B_ * G_ * SO3 + 255) / 256, 256>>>();

    // 7) so3->so3 conv -> output
    stageH_kernel<<<(B_ * SO3 + 255) / 256, 256>>>(out);
}

// round 8
// speedup vs baseline: 2.9871x; 2.9871x over previous
#include <cuda_runtime.h>
#include <cuda_bf16.h>
#include <math.h>
#include <stdint.h>

typedef __nv_bfloat16 bf16;

// ---------------------------------------------------------------------------
// Problem constants
// ---------------------------------------------------------------------------
static constexpr int B_   = 128;
static constexpr int C_   = 2048;
static constexpr int HW   = 49;
static constexpr int FIN  = 512;
static constexpr int G_   = 8;
static constexpr int NP   = 192;
static constexpr int S2   = 49;
static constexpr int SO3  = 455;
static constexpr int NG   = 4000;
static constexpr int GI   = 392;                // G_*S2
static constexpr size_t BC = (size_t)B_ * C_;   // 262144

static constexpr float RS192 = 0.07216878364870323f;
static constexpr float RS512 = 0.04419417382415922f;

// ---------------------------------------------------------------------------
// Scratch (device globals; runtime allocation is forbidden)
// ---------------------------------------------------------------------------
__device__ float d_P[HW * S2];
__device__ float d_q[S2];
__device__ float d_psi[FIN * GI];
__device__ float d_bpsi[GI];
__device__ float d_psi2[G_ * SO3];
__device__ float d_W2c[C_ * 448];                 // [c][gi pad 448]
__device__ float d_W2t[7 * 104 * C_];             // [l][g*d+u pad 104][c]
__device__ float d_AD[(size_t)49 * BC];           // [i][b*2048+c]
__device__ float d_partD[(size_t)2 * 49 * 128 * 104];
__device__ float d_x4[1024 * 512];                // [b*8+g][so3 pad 512]
__device__ float d_gact[(size_t)1024 * 4096];     // [b*8+g][ng pad 4096]
__device__ float d_part6[(size_t)4 * 1024 * 512];
__device__ float d_x5[1024 * SO3];

__constant__ int c_off2[8] = {0, 1, 10, 35, 84, 165, 286, 455};
__constant__ int c_l_of_i[49] = {
    0, 1,1,1, 2,2,2,2,2, 3,3,3,3,3,3,3, 4,4,4,4,4,4,4,4,4,
    5,5,5,5,5,5,5,5,5,5,5, 6,6,6,6,6,6,6,6,6,6,6,6,6};

// ---------------------------------------------------------------------------
// helpers
// ---------------------------------------------------------------------------
__device__ __forceinline__ uint32_t smem_u32(const void* p) {
    uint32_t a;
    asm("{ .reg .u64 t; cvta.to.shared.u64 t, %1; cvt.u32.u64 %0, t; }"
        : "=r"(a) : "l"(p));
    return a;
}

__device__ __forceinline__ void ldsm4(uint32_t addr, uint32_t r[4]) {
    asm volatile("ldmatrix.sync.aligned.m8n8.x4.shared.b16 {%0,%1,%2,%3}, [%4];"
                 : "=r"(r[0]), "=r"(r[1]), "=r"(r[2]), "=r"(r[3]) : "r"(addr));
}

__device__ __forceinline__ void mma16816(float c[4], const uint32_t a[4],
                                         const uint32_t b[2]) {
    asm volatile(
        "mma.sync.aligned.m16n8k16.row.col.f32.bf16.bf16.f32 "
        "{%0,%1,%2,%3}, {%4,%5,%6,%7}, {%8,%9}, {%0,%1,%2,%3};"
        : "+f"(c[0]), "+f"(c[1]), "+f"(c[2]), "+f"(c[3])
        : "r"(a[0]), "r"(a[1]), "r"(a[2]), "r"(a[3]), "r"(b[0]), "r"(b[1]));
}

// ---------------------------------------------------------------------------
// mma.sync GEMM engine: C[M=128/CTA][NT] = alpha * A @ B^T, fp32 in/out,
// 3-term bf16 hi/lo split (Ah*Bh + Ah*Bl + Al*Bh), fp32 accumulation.
// A src: [m][k] (ATRANS=0) or [k][m] (ATRANS=1), leading dim lda.
// B src: [n][k] (BTRANS=0) or [k][n] (BTRANS=1), leading dim ldb.
// C: [m][n] ldc, or OTRANS: [n][m] ldc.
// grid: (nTile, mTile, z);  batch = z>>zdiv, sub = z & ((1<<zdiv)-1);
// k range = [sub*kstride, +kchunks*32), zero-filled beyond Kreal.
// 256 threads = 8 warps (4 m x 2 n), warp tile 32 x NT/2, BK=32.
// ---------------------------------------------------------------------------
template<bool ATRANS, bool BTRANS, bool OTRANS, bool RELU, int NT, bool LSEL>
__global__ void __launch_bounds__(256) mmag(
    const float* __restrict__ A, const float* __restrict__ Bsrc, float* __restrict__ C,
    int lda, int ldb, int ldc, int Kreal, int Nreal, float alpha,
    int kchunks, int kstride, int zdiv,
    size_t astride, size_t bstride, size_t cstride, size_t cstride2)
{
    constexpr int NT16 = NT / 16;      // n-fragments (8 wide) per warp
    __shared__ bf16 sA[2][128][40];    // [split][m][k], stride 80B (bank-safe)
    __shared__ bf16 sB[2][NT][40];

    const int tid = threadIdx.x;
    const int z = blockIdx.z;
    const int batch = z >> zdiv;
    const int sub = z - (batch << zdiv);
    const float* Ap = A + (size_t)batch * astride;
    const float* Bp = Bsrc + (LSEL ? (size_t)c_l_of_i[batch] * bstride
                                   : (size_t)batch * bstride);
    float* Cp = C + (size_t)batch * cstride + (size_t)sub * cstride2;
    const int kbeg = sub * kstride;
    const int r0 = blockIdx.y * 128;
    const int n0 = blockIdx.x * NT;

    const int lane = tid & 31, w = tid >> 5;
    const int wm = w & 3, wn = w >> 2;
    const int rA = wm * 32;
    const int nbase = wn * (NT / 2);

    float acc[2][NT16][4];
    #pragma unroll
    for (int mi = 0; mi < 2; mi++)
        #pragma unroll
        for (int ni = 0; ni < NT16; ni++)
            #pragma unroll
            for (int j = 0; j < 4; j++) acc[mi][ni][j] = 0.f;

    for (int ch = 0; ch < kchunks; ch++) {
        const int kc = kbeg + ch * 32;
        __syncthreads();
        // ---- load + split A tile: 128 x 32 ----
        #pragma unroll
        for (int it = 0; it < 16; it++) {
            int idx = it * 256 + tid;
            int r, kk;
            if (ATRANS) { r = idx & 127; kk = idx >> 7; }
            else        { kk = idx & 31; r = idx >> 5;  }
            int gk = kc + kk;
            float v = 0.f;
            if (gk < Kreal)
                v = ATRANS ? Ap[(size_t)gk * lda + (r0 + r)]
                           : Ap[(size_t)(r0 + r) * lda + gk];
            bf16 h = __float2bfloat16(v);
            sA[0][r][kk] = h;
            sA[1][r][kk] = __float2bfloat16(v - __bfloat162float(h));
        }
        // ---- load + split B tile: NT x 32 ----
        #pragma unroll
        for (int it = 0; it < NT / 8; it++) {
            int idx = it * 256 + tid;
            int n, kk;
            if (BTRANS) { n = idx & (NT - 1); kk = idx >> (NT == 128 ? 7 : 6); }
            else        { kk = idx & 31;      n = idx >> 5; }
            int gk = kc + kk, gn = n0 + n;
            float v = 0.f;
            if (gk < Kreal && gn < Nreal)
                v = BTRANS ? Bp[(size_t)gk * ldb + gn]
                           : Bp[(size_t)gn * ldb + gk];
            bf16 h = __float2bfloat16(v);
            sB[0][n][kk] = h;
            sB[1][n][kk] = __float2bfloat16(v - __bfloat162float(h));
        }
        __syncthreads();
        // ---- compute: two k16 steps ----
        #pragma unroll
        for (int kk = 0; kk < 32; kk += 16) {
            uint32_t aH[2][4], aL[2][4];
            const int arow = rA + (lane & 7) + ((lane >> 3) & 1) * 8;
            const int akc  = kk + (lane >> 4) * 8;
            #pragma unroll
            for (int mi = 0; mi < 2; mi++) {
                ldsm4(smem_u32(&sA[0][arow + mi * 16][akc]), aH[mi]);
                ldsm4(smem_u32(&sA[1][arow + mi * 16][akc]), aL[mi]);
            }
            #pragma unroll
            for (int np = 0; np < NT16 / 2; np++) {
                uint32_t bH[4], bL[4];
                const int brow = nbase + np * 16 + (lane >> 4) * 8 + (lane & 7);
                const int bkc  = kk + ((lane >> 3) & 1) * 8;
                ldsm4(smem_u32(&sB[0][brow][bkc]), bH);
                ldsm4(smem_u32(&sB[1][brow][bkc]), bL);
                #pragma unroll
                for (int mi = 0; mi < 2; mi++) {
                    #pragma unroll
                    for (int h = 0; h < 2; h++) {
                        int ni = 2 * np + h;
                        mma16816(acc[mi][ni], aH[mi], &bH[2 * h]);
                        mma16816(acc[mi][ni], aH[mi], &bL[2 * h]);
                        mma16816(acc[mi][ni], aL[mi], &bH[2 * h]);
                    }
                }
            }
        }
    }

    // ---- epilogue ----
    const int g = lane >> 2, tg = lane & 3;
    #pragma unroll
    for (int mi = 0; mi < 2; mi++) {
        #pragma unroll
        for (int ni = 0; ni < NT16; ni++) {
            int row = r0 + rA + mi * 16 + g;
            int col = n0 + nbase + ni * 8 + tg * 2;
            #pragma unroll
            for (int j = 0; j < 4; j++) {
                int rr = row + (j >> 1) * 8;
                int nn = col + (j & 1);
                if (nn < Nreal) {
                    float v = alpha * acc[mi][ni][j];
                    if (RELU) v = fmaxf(v, 0.f);
                    if (OTRANS) Cp[(size_t)nn * ldc + rr] = v;
                    else        Cp[(size_t)rr * ldc + nn] = v;
                }
            }
        }
    }
}

// ---------------------------------------------------------------------------
// Small kernels
// ---------------------------------------------------------------------------
__global__ void k_P(const float* __restrict__ proj_w, const float* __restrict__ proj_Y) {
    int t = blockIdx.x * blockDim.x + threadIdx.x;
    if (t >= HW * S2) return;
    int hw = t / S2, i = t % S2;
    const float* wr = proj_w + hw * NP;
    float acc = 0.f;
    #pragma unroll 8
    for (int n = 0; n < NP; n++) acc += wr[n] * proj_Y[n * S2 + i];
    d_P[t] = acc * RS192;
}

__global__ void k_q() {
    int i = threadIdx.x;
    if (i >= S2) return;
    float a = 0.f;
    for (int hw = 0; hw < HW; hw++) a += d_P[hw * S2 + i];
    d_q[i] = a;
}

__global__ void k_psi(const float* __restrict__ fs_w, const float* __restrict__ fs_Y) {
    int t = blockIdx.x * blockDim.x + threadIdx.x;
    if (t >= FIN * GI) return;
    int i = t % S2, fg = t / S2;
    const float* wr = fs_w + (size_t)fg * NP;
    float acc = 0.f;
    #pragma unroll 8
    for (int n = 0; n < NP; n++) acc += wr[n] * fs_Y[n * S2 + i];
    d_psi[t] = acc * RS192;
}

__global__ void k_bpsi(const float* __restrict__ conv_b) {
    int w = (blockIdx.x * blockDim.x + threadIdx.x) >> 5;
    int lane = threadIdx.x & 31;
    if (w >= GI) return;
    float acc = 0.f;
    for (int f = lane; f < FIN; f += 32) acc += conv_b[f] * d_psi[f * GI + w];
    #pragma unroll
    for (int o = 16; o; o >>= 1) acc += __shfl_xor_sync(0xFFFFFFFFu, acc, o);
    if (lane == 0) d_bpsi[w] = acc * RS512;
}

__global__ void k_psi2(const float* __restrict__ so3_w, const float* __restrict__ so3_D) {
    int w = (blockIdx.x * blockDim.x + threadIdx.x) >> 5;
    int lane = threadIdx.x & 31;
    if (w >= G_ * SO3) return;
    int f = w / SO3, i = w % SO3;
    float acc = 0.f;
    for (int n = lane; n < NP; n += 32) acc += so3_w[f * NP + n] * so3_D[n * SO3 + i];
    #pragma unroll
    for (int o = 16; o; o >>= 1) acc += __shfl_xor_sync(0xFFFFFFFFu, acc, o);
    if (lane == 0) d_psi2[w] = acc * RS192;
}

// W2c [c][gi pad448] -> W2t [l][j=g*d+u pad104][c] (zero pad)
__global__ void k_w2t() {
    int t = blockIdx.x * blockDim.x + threadIdx.x;
    if (t >= 7 * 104 * C_) return;
    int l = t / (104 * C_);
    int r = t - l * 104 * C_;
    int j = r / C_, c = r - j * C_;
    int d = 2 * l + 1;
    float v = 0.f;
    if (j < 8 * d) {
        int g = j / d, u = j - g * d;
        v = d_W2c[(size_t)c * 448 + g * S2 + l * l + u];
    }
    d_W2t[t] = v;
}

// partD (2 k-halves) + bias -> x4 [1024][512] (zero pad cols >= 455)
__global__ void k_x4() {
    int t = blockIdx.x * blockDim.x + threadIdx.x;
    if (t >= 1024 * 512) return;
    int row = t >> 9, col = t & 511;
    int b = row >> 3, g = row & 7;
    float v = 0.f;
    if (col < SO3) {
        int l = 6;
        while (col < c_off2[l]) l--;
        int d = 2 * l + 1, r = col - c_off2[l];
        int u = r / d, m = r - u * d, i = l * l + m;
        size_t o = (size_t)i * 128 * 104 + (size_t)b * 104 + g * d + u;
        v = d_partD[o] + d_partD[o + (size_t)49 * 128 * 104]
            + d_bpsi[g * S2 + l * l + u] * d_q[l * l + m];
    }
    d_x4[t] = v;
}

__global__ void k_red6() {
    int t = blockIdx.x * blockDim.x + threadIdx.x;
    if (t >= 1024 * SO3) return;
    int row = t / SO3, col = t - row * SO3;
    float s = 0.f;
    #pragma unroll
    for (int zz = 0; zz < 4; zz++)
        s += d_part6[(size_t)zz * 1024 * 512 + (size_t)row * 512 + col];
    d_x5[t] = s;
}

__global__ void stageH_kernel(float* __restrict__ out) {
    int t = blockIdx.x * blockDim.x + threadIdx.x;
    if (t >= B_ * SO3) return;
    int b = t / SO3, j = t - b * SO3;
    int l = 6;
    while (j < c_off2[l]) l--;
    int d = 2 * l + 1;
    int r = j - c_off2[l];
    int v = r / d, m = r - v * d;
    float acc = 0.f;
    #pragma unroll
    for (int f = 0; f < G_; f++) {
        const float* xr = d_x5 + (size_t)(b * G_ + f) * SO3 + c_off2[l];
        const float* pr = d_psi2 + f * SO3 + c_off2[l];
        for (int u = 0; u < d; u++) acc += xr[u * d + m] * pr[u * d + v];
    }
    out[t] = acc * (1.0f / sqrtf(8.0f * d));
}

// ---------------------------------------------------------------------------
// Host launcher
// ---------------------------------------------------------------------------
extern "C" void kernel_launch(void* const* d_in, const int* in_sizes, int n_in,
                              void* d_out, int out_size) {
    const float* fmap     = (const float*)d_in[0];
    const float* conv_w   = (const float*)d_in[1];
    const float* conv_b   = (const float*)d_in[2];
    const float* proj_w   = (const float*)d_in[3];
    const float* proj_Y   = (const float*)d_in[4];
    const float* fs_w     = (const float*)d_in[5];
    const float* fs_Y     = (const float*)d_in[6];
    const float* act_to   = (const float*)d_in[7];
    const float* act_from = (const float*)d_in[8];
    const float* so3_w    = (const float*)d_in[9];
    const float* so3_D    = (const float*)d_in[10];
    float* out = (float*)d_out;

    float *pP, *pPsi, *pW2c, *pW2t, *pAD, *pPartD, *pX4, *pGact, *pPart6;
    cudaGetSymbolAddress((void**)&pP,     d_P);
    cudaGetSymbolAddress((void**)&pPsi,   d_psi);
    cudaGetSymbolAddress((void**)&pW2c,   d_W2c);
    cudaGetSymbolAddress((void**)&pW2t,   d_W2t);
    cudaGetSymbolAddress((void**)&pAD,    d_AD);
    cudaGetSymbolAddress((void**)&pPartD, d_partD);
    cudaGetSymbolAddress((void**)&pX4,    d_x4);
    cudaGetSymbolAddress((void**)&pGact,  d_gact);
    cudaGetSymbolAddress((void**)&pPart6, d_part6);

    // small precomputes
    k_P   <<<(HW * S2 + 255) / 256, 256>>>(proj_w, proj_Y);
    k_q   <<<1, 64>>>();
    k_psi <<<(FIN * GI + 255) / 256, 256>>>(fs_w, fs_Y);
    k_bpsi<<<(GI * 32 + 127) / 128, 128>>>(conv_b);
    k_psi2<<<(G_ * SO3 * 32 + 127) / 128, 128>>>(so3_w, so3_D);

    // W2c = RS512 * conv_w^T @ psi   (M=2048, N=392, K=512)
    mmag<true, true, false, false, 64, false><<<dim3(7, 16, 1), 256>>>(
        conv_w, pPsi, pW2c, C_, GI, 448, FIN, GI, RS512, 16, 0, 0, 0, 0, 0, 0);
    k_w2t<<<(7 * 104 * C_ + 255) / 256, 256>>>();

    // AD[i][b*2048+c] = (fmap @ P)^T   (M=262144, N=49, K=49) — OTRANS store
    mmag<false, true, true, false, 64, false><<<dim3(1, 2048, 1), 256>>>(
        fmap, pP, pAD, HW, S2, (int)BC, HW, S2, 1.f, 2, 0, 0, 0, 0, 0, 0);

    // stageD: 49 batched GEMMs (M=128, N=104, K=2048), split-K x2 -> partD
    mmag<false, false, false, false, 128, true><<<dim3(1, 1, 98), 256>>>(
        pAD, pW2t, pPartD, C_, C_, 104, C_, 104, 1.f, 32, 1024, 1,
        BC, (size_t)104 * C_, (size_t)128 * 104, (size_t)49 * 128 * 104);
    k_x4<<<(1024 * 512 + 255) / 256, 256>>>();

    // stage5: gact = relu(x4 @ act_to)   (M=1024, N=4000, K=455)
    mmag<false, true, false, true, 128, false><<<dim3(32, 8, 1), 256>>>(
        pX4, act_to, pGact, 512, NG, 4096, SO3, NG, 1.f, 15, 0, 0, 0, 0, 0, 0);

    // stage6: part6[z] = gact @ act_from (split-K x4)  (M=1024, N=455, K=4000)
    mmag<false, true, false, false, 128, false><<<dim3(4, 8, 4), 256>>>(
        pGact, act_from, pPart6, 4096, SO3, 512, NG, SO3, 1.f, 32, 1024, 2,
        0, 0, 0, (size_t)1024 * 512);
    k_red6<<<(1024 * SO3 + 255) / 256, 256>>>();

    // stage H
    stageH_kernel<<<(B_ * SO3 + 255) / 256, 256>>>(out);
}

// round 9
// speedup vs baseline: 3.8356x; 1.2841x over previous
#include <cuda_runtime.h>
#include <cuda_bf16.h>
#include <math.h>
#include <stdint.h>

typedef __nv_bfloat16 bf16;

// ---------------------------------------------------------------------------
// Problem constants
// ---------------------------------------------------------------------------
static constexpr int B_   = 128;
static constexpr int C_   = 2048;
static constexpr int HW   = 49;
static constexpr int FIN  = 512;
static constexpr int G_   = 8;
static constexpr int NP   = 192;
static constexpr int S2   = 49;
static constexpr int SO3  = 455;
static constexpr int NG   = 4000;
static constexpr int GI   = 392;                // G_*S2
static constexpr size_t BC = (size_t)B_ * C_;   // 262144

static constexpr float RS192 = 0.07216878364870323f;
static constexpr float RS512 = 0.04419417382415922f;

// ---------------------------------------------------------------------------
// Scratch (device globals; runtime allocation is forbidden)
// ---------------------------------------------------------------------------
__device__ float d_P[HW * S2];
__device__ float d_q[S2];
__device__ float d_psi[FIN * GI];
__device__ float d_bpsi[GI];
__device__ float d_psi2[G_ * SO3];
__device__ float d_W2c[C_ * 448];                    // [c][gi pad 448]

// hi/lo bf16 planes (pre-split operands for the pipelined GEMMs)
__device__ __align__(16) bf16 d_ADh[(size_t)49 * BC];   // [i][b*2048+c]
__device__ __align__(16) bf16 d_ADl[(size_t)49 * BC];
__device__ __align__(16) bf16 d_W2th[7 * 128 * C_];     // [l][j pad128][c]
__device__ __align__(16) bf16 d_W2tl[7 * 128 * C_];
__device__ __align__(16) bf16 d_x4h[1024 * 512];        // [b*8+g][so3 pad512]
__device__ __align__(16) bf16 d_x4l[1024 * 512];
__device__ __align__(16) bf16 d_bt5h[(size_t)4096 * 480]; // act_to^T planes
__device__ __align__(16) bf16 d_bt5l[(size_t)4096 * 480];
__device__ __align__(16) bf16 d_gacth[(size_t)1024 * 4096];
__device__ __align__(16) bf16 d_gactl[(size_t)1024 * 4096];
__device__ __align__(16) bf16 d_bt6h[(size_t)512 * 4096]; // act_from^T planes
__device__ __align__(16) bf16 d_bt6l[(size_t)512 * 4096];

__device__ float d_partD[(size_t)4 * 49 * 128 * 104];
__device__ float d_part6[(size_t)8 * 1024 * 512];
__device__ float d_x5[1024 * SO3];

__constant__ int c_off2[8] = {0, 1, 10, 35, 84, 165, 286, 455};
__constant__ int c_l_of_i[49] = {
    0, 1,1,1, 2,2,2,2,2, 3,3,3,3,3,3,3, 4,4,4,4,4,4,4,4,4,
    5,5,5,5,5,5,5,5,5,5,5, 6,6,6,6,6,6,6,6,6,6,6,6,6};

// ---------------------------------------------------------------------------
// helpers
// ---------------------------------------------------------------------------
__device__ __forceinline__ uint32_t smem_u32(const void* p) {
    uint32_t a;
    asm("{ .reg .u64 t; cvta.to.shared.u64 t, %1; cvt.u32.u64 %0, t; }"
        : "=r"(a) : "l"(p));
    return a;
}

__device__ __forceinline__ void ldsm4(uint32_t addr, uint32_t r[4]) {
    asm volatile("ldmatrix.sync.aligned.m8n8.x4.shared.b16 {%0,%1,%2,%3}, [%4];"
                 : "=r"(r[0]), "=r"(r[1]), "=r"(r[2]), "=r"(r[3]) : "r"(addr));
}

__device__ __forceinline__ void mma16816(float c[4], const uint32_t a[4],
                                         const uint32_t b[2]) {
    asm volatile(
        "mma.sync.aligned.m16n8k16.row.col.f32.bf16.bf16.f32 "
        "{%0,%1,%2,%3}, {%4,%5,%6,%7}, {%8,%9}, {%0,%1,%2,%3};"
        : "+f"(c[0]), "+f"(c[1]), "+f"(c[2]), "+f"(c[3])
        : "r"(a[0]), "r"(a[1]), "r"(a[2]), "r"(a[3]), "r"(b[0]), "r"(b[1]));
}

__device__ __forceinline__ void split2(float v, bf16& h, bf16& l) {
    h = __float2bfloat16(v);
    l = __float2bfloat16(v - __bfloat162float(h));
}

__device__ __forceinline__ uint32_t pack2(bf16 a, bf16 b) {
    return (uint32_t)__bfloat16_as_ushort(a) |
           ((uint32_t)__bfloat16_as_ushort(b) << 16);
}

// ---------------------------------------------------------------------------
// Engine A (fp32 inputs, split-on-load; used for W2 and AD GEMMs) — R8-proven.
// ---------------------------------------------------------------------------
template<bool ATRANS, bool BTRANS, bool OTRANS, int NT, bool PACKOUT>
__global__ void __launch_bounds__(256) mmag_f(
    const float* __restrict__ A, const float* __restrict__ Bsrc,
    float* __restrict__ C, bf16* __restrict__ Ch, bf16* __restrict__ Cl,
    int lda, int ldb, int ldc, int Kreal, int Nreal, float alpha, int kchunks)
{
    constexpr int NT16 = NT / 16;
    __shared__ bf16 sA[2][128][40];
    __shared__ bf16 sB[2][NT][40];

    const int tid = threadIdx.x;
    const int r0 = blockIdx.y * 128;
    const int n0 = blockIdx.x * NT;
    const int lane = tid & 31, w = tid >> 5;
    const int wm = w & 3, wn = w >> 2;
    const int rA = wm * 32;
    const int nbase = wn * (NT / 2);

    float acc[2][NT16][4];
    #pragma unroll
    for (int mi = 0; mi < 2; mi++)
        #pragma unroll
        for (int ni = 0; ni < NT16; ni++)
            #pragma unroll
            for (int j = 0; j < 4; j++) acc[mi][ni][j] = 0.f;

    for (int ch = 0; ch < kchunks; ch++) {
        const int kc = ch * 32;
        __syncthreads();
        #pragma unroll
        for (int it = 0; it < 16; it++) {
            int idx = it * 256 + tid;
            int r, kk;
            if (ATRANS) { r = idx & 127; kk = idx >> 7; }
            else        { kk = idx & 31; r = idx >> 5;  }
            int gk = kc + kk;
            float v = 0.f;
            if (gk < Kreal)
                v = ATRANS ? A[(size_t)gk * lda + (r0 + r)]
                           : A[(size_t)(r0 + r) * lda + gk];
            split2(v, sA[0][r][kk], sA[1][r][kk]);
        }
        #pragma unroll
        for (int it = 0; it < NT / 8; it++) {
            int idx = it * 256 + tid;
            int n, kk;
            if (BTRANS) { n = idx & (NT - 1); kk = idx >> (NT == 128 ? 7 : 6); }
            else        { kk = idx & 31;      n = idx >> 5; }
            int gk = kc + kk, gn = n0 + n;
            float v = 0.f;
            if (gk < Kreal && gn < Nreal)
                v = BTRANS ? Bsrc[(size_t)gk * ldb + gn]
                           : Bsrc[(size_t)gn * ldb + gk];
            split2(v, sB[0][n][kk], sB[1][n][kk]);
        }
        __syncthreads();
        #pragma unroll
        for (int kk = 0; kk < 32; kk += 16) {
            uint32_t aH[2][4], aL[2][4];
            const int arow = rA + (lane & 7) + ((lane >> 3) & 1) * 8;
            const int akc  = kk + (lane >> 4) * 8;
            #pragma unroll
            for (int mi = 0; mi < 2; mi++) {
                ldsm4(smem_u32(&sA[0][arow + mi * 16][akc]), aH[mi]);
                ldsm4(smem_u32(&sA[1][arow + mi * 16][akc]), aL[mi]);
            }
            #pragma unroll
            for (int np = 0; np < NT16 / 2; np++) {
                uint32_t bH[4], bL[4];
                const int brow = nbase + np * 16 + (lane >> 4) * 8 + (lane & 7);
                const int bkc  = kk + ((lane >> 3) & 1) * 8;
                ldsm4(smem_u32(&sB[0][brow][bkc]), bH);
                ldsm4(smem_u32(&sB[1][brow][bkc]), bL);
                #pragma unroll
                for (int mi = 0; mi < 2; mi++) {
                    #pragma unroll
                    for (int h = 0; h < 2; h++) {
                        int ni = 2 * np + h;
                        mma16816(acc[mi][ni], aH[mi], &bH[2 * h]);
                        mma16816(acc[mi][ni], aH[mi], &bL[2 * h]);
                        mma16816(acc[mi][ni], aL[mi], &bH[2 * h]);
                    }
                }
            }
        }
    }

    const int g2 = lane >> 2, tg = lane & 3;
    #pragma unroll
    for (int mi = 0; mi < 2; mi++) {
        #pragma unroll
        for (int ni = 0; ni < NT16; ni++) {
            int row = r0 + rA + mi * 16 + g2;
            int col = n0 + nbase + ni * 8 + tg * 2;
            #pragma unroll
            for (int j = 0; j < 4; j++) {
                int rr = row + (j >> 1) * 8;
                int nn = col + (j & 1);
                if (nn < Nreal) {
                    float v = alpha * acc[mi][ni][j];
                    size_t o = OTRANS ? (size_t)nn * ldc + rr
                                      : (size_t)rr * ldc + nn;
                    if (PACKOUT) {
                        bf16 h, l; split2(v, h, l);
                        Ch[o] = h; Cl[o] = l;
                    } else {
                        C[o] = v;
                    }
                }
            }
        }
    }
}

// ---------------------------------------------------------------------------
// Engine B (pre-split bf16 planes, cp.async double-buffered) — stageD/5/6.
// NT = 128. C[M=128][128] per CTA, 3-term hi/lo, fp32 accum.
// All operands zero-padded in global: no guards in loader.
// ---------------------------------------------------------------------------
template<bool RELU, bool PACKOUT, bool LSEL>
__global__ void __launch_bounds__(256) mmag_p(
    const bf16* __restrict__ Ah, const bf16* __restrict__ Al,
    const bf16* __restrict__ Bh, const bf16* __restrict__ Bl,
    float* __restrict__ C, bf16* __restrict__ Ch, bf16* __restrict__ Cl,
    int lda, int ldb, int ldc, int Nreal,
    int kchunks, int kstride, int zdiv,
    size_t astride, size_t bstride, size_t cstride, size_t cstride2)
{
    extern __shared__ bf16 S[];   // sA[2buf][2pl][128][40] then sB same: 81920 B
    const int tid = threadIdx.x;
    const int z = blockIdx.z;
    const int batch = z >> zdiv;
    const int sub = z - (batch << zdiv);
    const bf16* Aph = Ah + (size_t)batch * astride;
    const bf16* Apl = Al + (size_t)batch * astride;
    const size_t boff = (LSEL ? (size_t)c_l_of_i[batch] : (size_t)batch) * bstride;
    const bf16* Bph = Bh + boff;
    const bf16* Bpl = Bl + boff;
    float* Cp = C + (size_t)batch * cstride + (size_t)sub * cstride2;
    const int kbeg = sub * kstride;
    const int r0 = blockIdx.y * 128;
    const int n0 = blockIdx.x * 128;
    const int lane = tid & 31, w = tid >> 5;
    const int rA = (w & 3) * 32;
    const int nbase = (w >> 2) * 64;
    const uint32_t sbase = smem_u32(S);
    constexpr uint32_t SBOFF = 2 * 2 * 128 * 40 * 2;   // bytes

    float acc[2][8][4];
    #pragma unroll
    for (int mi = 0; mi < 2; mi++)
        #pragma unroll
        for (int ni = 0; ni < 8; ni++)
            #pragma unroll
            for (int j = 0; j < 4; j++) acc[mi][ni][j] = 0.f;

    // async copy of one 128x32 x2-plane tile pair into buffer `buf`
    auto copyin = [&](int buf, int kc) {
        #pragma unroll
        for (int it = 0; it < 8; it++) {
            int idx = it * 256 + tid;
            int q = idx & 7, r = (idx >> 3) & 127, p = idx >> 10;
            const bf16* g = (p ? Apl : Aph) + (size_t)(r0 + r) * lda + kc + q * 4;
            uint32_t d = sbase + (((buf * 2 + p) * 128 + r) * 40 + q * 4) * 2;
            asm volatile("cp.async.ca.shared.global [%0], [%1], 8;"
                         :: "r"(d), "l"(g));
        }
        #pragma unroll
        for (int it = 0; it < 8; it++) {
            int idx = it * 256 + tid;
            int q = idx & 7, r = (idx >> 3) & 127, p = idx >> 10;
            const bf16* g = (p ? Bpl : Bph) + (size_t)(n0 + r) * ldb + kc + q * 4;
            uint32_t d = sbase + SBOFF + (((buf * 2 + p) * 128 + r) * 40 + q * 4) * 2;
            asm volatile("cp.async.ca.shared.global [%0], [%1], 8;"
                         :: "r"(d), "l"(g));
        }
        asm volatile("cp.async.commit_group;" ::: "memory");
    };

    int buf = 0;
    copyin(0, kbeg);

    for (int ch = 0; ch < kchunks; ch++) {
        if (ch + 1 < kchunks) {
            copyin(buf ^ 1, kbeg + (ch + 1) * 32);
            asm volatile("cp.async.wait_group 1;" ::: "memory");
        } else {
            asm volatile("cp.async.wait_group 0;" ::: "memory");
        }
        __syncthreads();

        #pragma unroll
        for (int kk = 0; kk < 32; kk += 16) {
            uint32_t aH[2][4], aL[2][4];
            const int arow = rA + (lane & 7) + ((lane >> 3) & 1) * 8;
            const int akc  = kk + (lane >> 4) * 8;
            #pragma unroll
            for (int mi = 0; mi < 2; mi++) {
                uint32_t a0 = sbase + (((buf * 2 + 0) * 128 + arow + mi * 16) * 40 + akc) * 2;
                uint32_t a1 = sbase + (((buf * 2 + 1) * 128 + arow + mi * 16) * 40 + akc) * 2;
                ldsm4(a0, aH[mi]);
                ldsm4(a1, aL[mi]);
            }
            #pragma unroll
            for (int np = 0; np < 4; np++) {
                uint32_t bH[4], bL[4];
                const int brow = nbase + np * 16 + (lane >> 4) * 8 + (lane & 7);
                const int bkc  = kk + ((lane >> 3) & 1) * 8;
                uint32_t b0 = sbase + SBOFF + (((buf * 2 + 0) * 128 + brow) * 40 + bkc) * 2;
                uint32_t b1 = sbase + SBOFF + (((buf * 2 + 1) * 128 + brow) * 40 + bkc) * 2;
                ldsm4(b0, bH);
                ldsm4(b1, bL);
                #pragma unroll
                for (int mi = 0; mi < 2; mi++) {
                    #pragma unroll
                    for (int h = 0; h < 2; h++) {
                        int ni = 2 * np + h;
                        mma16816(acc[mi][ni], aH[mi], &bH[2 * h]);
                        mma16816(acc[mi][ni], aH[mi], &bL[2 * h]);
                        mma16816(acc[mi][ni], aL[mi], &bH[2 * h]);
                    }
                }
            }
        }
        __syncthreads();
        buf ^= 1;
    }

    // epilogue
    const int g2 = lane >> 2, tg = lane & 3;
    #pragma unroll
    for (int mi = 0; mi < 2; mi++) {
        #pragma unroll
        for (int ni = 0; ni < 8; ni++) {
            int row = r0 + rA + mi * 16 + g2;
            int col = n0 + nbase + ni * 8 + tg * 2;
            float v[4];
            #pragma unroll
            for (int j = 0; j < 4; j++) {
                v[j] = acc[mi][ni][j];
                if (RELU) v[j] = fmaxf(v[j], 0.f);
            }
            if (PACKOUT) {
                #pragma unroll
                for (int h = 0; h < 2; h++) {
                    int rr = row + h * 8;
                    bf16 h0, l0, h1, l1;
                    split2(v[2 * h + 0], h0, l0);
                    split2(v[2 * h + 1], h1, l1);
                    *(uint32_t*)&Ch[(size_t)rr * ldc + col] = pack2(h0, h1);
                    *(uint32_t*)&Cl[(size_t)rr * ldc + col] = pack2(l0, l1);
                }
            } else {
                #pragma unroll
                for (int j = 0; j < 4; j++) {
                    int rr = row + (j >> 1) * 8;
                    int nn = col + (j & 1);
                    if (nn < Nreal) Cp[(size_t)rr * ldc + nn] = v[j];
                }
            }
        }
    }
}

// ---------------------------------------------------------------------------
// Small kernels
// ---------------------------------------------------------------------------
__global__ void k_P(const float* __restrict__ proj_w, const float* __restrict__ proj_Y) {
    int t = blockIdx.x * blockDim.x + threadIdx.x;
    if (t >= HW * S2) return;
    int hw = t / S2, i = t % S2;
    const float* wr = proj_w + hw * NP;
    float acc = 0.f;
    #pragma unroll 8
    for (int n = 0; n < NP; n++) acc += wr[n] * proj_Y[n * S2 + i];
    d_P[t] = acc * RS192;
}

__global__ void k_q() {
    int i = threadIdx.x;
    if (i >= S2) return;
    float a = 0.f;
    for (int hw = 0; hw < HW; hw++) a += d_P[hw * S2 + i];
    d_q[i] = a;
}

__global__ void k_psi(const float* __restrict__ fs_w, const float* __restrict__ fs_Y) {
    int t = blockIdx.x * blockDim.x + threadIdx.x;
    if (t >= FIN * GI) return;
    int i = t % S2, fg = t / S2;
    const float* wr = fs_w + (size_t)fg * NP;
    float acc = 0.f;
    #pragma unroll 8
    for (int n = 0; n < NP; n++) acc += wr[n] * fs_Y[n * S2 + i];
    d_psi[t] = acc * RS192;
}

// coalesced: thread t handles output t, lanes read consecutive psi columns
__global__ void k_bpsi(const float* __restrict__ conv_b) {
    int t = blockIdx.x * blockDim.x + threadIdx.x;
    if (t >= GI) return;
    float acc = 0.f;
    #pragma unroll 8
    for (int f = 0; f < FIN; f++) acc += conv_b[f] * d_psi[f * GI + t];
    d_bpsi[t] = acc * RS512;
}

__global__ void k_psi2(const float* __restrict__ so3_w, const float* __restrict__ so3_D) {
    int w = (blockIdx.x * blockDim.x + threadIdx.x) >> 5;
    int lane = threadIdx.x & 31;
    if (w >= G_ * SO3) return;
    int f = w / SO3, i = w % SO3;
    float acc = 0.f;
    for (int n = lane; n < NP; n += 32) acc += so3_w[f * NP + n] * so3_D[n * SO3 + i];
    #pragma unroll
    for (int o = 16; o; o >>= 1) acc += __shfl_xor_sync(0xFFFFFFFFu, acc, o);
    if (lane == 0) d_psi2[w] = acc * RS192;
}

// tiled transpose + hi/lo split: out[n][k] = in[k][n], zero-padded
__global__ void k_tpose(const float* __restrict__ in, bf16* __restrict__ oh,
                        bf16* __restrict__ ol, int inR, int inC, int ldo) {
    __shared__ float tl[32][33];
    int n0 = blockIdx.x * 32, k0 = blockIdx.y * 32;
    #pragma unroll
    for (int j = 0; j < 4; j++) {
        int k = k0 + threadIdx.y + j * 8, n = n0 + threadIdx.x;
        tl[threadIdx.y + j * 8][threadIdx.x] =
            (k < inR && n < inC) ? in[(size_t)k * inC + n] : 0.f;
    }
    __syncthreads();
    #pragma unroll
    for (int j = 0; j < 4; j++) {
        int n = n0 + threadIdx.y + j * 8, k = k0 + threadIdx.x;
        bf16 h, l;
        split2(tl[threadIdx.x][threadIdx.y + j * 8], h, l);
        oh[(size_t)n * ldo + k] = h;
        ol[(size_t)n * ldo + k] = l;
    }
}

// W2c [c][gi pad448] -> planes [l][j pad128][c]
__global__ void k_w2t() {
    int t = blockIdx.x * blockDim.x + threadIdx.x;
    if (t >= 7 * 128 * C_) return;
    int l = t / (128 * C_);
    int r = t - l * 128 * C_;
    int j = r / C_, c = r - j * C_;
    int d = 2 * l + 1;
    float v = 0.f;
    if (j < 8 * d) {
        int g = j / d, u = j - g * d;
        v = d_W2c[(size_t)c * 448 + g * S2 + l * l + u];
    }
    bf16 h, lo;
    split2(v, h, lo);
    d_W2th[t] = h;
    d_W2tl[t] = lo;
}

// partD (4 k-slabs) + bias -> x4 planes [1024][512] (zero pad cols >= 455)
__global__ void k_x4() {
    int t = blockIdx.x * blockDim.x + threadIdx.x;
    if (t >= 1024 * 512) return;
    int row = t >> 9, col = t & 511;
    int b = row >> 3, g = row & 7;
    float v = 0.f;
    if (col < SO3) {
        int l = 6;
        while (col < c_off2[l]) l--;
        int d = 2 * l + 1, r = col - c_off2[l];
        int u = r / d, m = r - u * d, i = l * l + m;
        size_t o = (size_t)i * 128 * 104 + (size_t)b * 104 + g * d + u;
        float s = 0.f;
        #pragma unroll
        for (int zz = 0; zz < 4; zz++)
            s += d_partD[o + (size_t)zz * 49 * 128 * 104];
        v = s + d_bpsi[g * S2 + l * l + u] * d_q[l * l + m];
    }
    bf16 h, lo;
    split2(v, h, lo);
    d_x4h[t] = h;
    d_x4l[t] = lo;
}

__global__ void k_red6() {
    int t = blockIdx.x * blockDim.x + threadIdx.x;
    if (t >= 1024 * SO3) return;
    int row = t / SO3, col = t - row * SO3;
    float s = 0.f;
    #pragma unroll
    for (int zz = 0; zz < 8; zz++)
        s += d_part6[(size_t)zz * 1024 * 512 + (size_t)row * 512 + col];
    d_x5[t] = s;
}

__global__ void stageH_kernel(float* __restrict__ out) {
    int t = blockIdx.x * blockDim.x + threadIdx.x;
    if (t >= B_ * SO3) return;
    int b = t / SO3, j = t - b * SO3;
    int l = 6;
    while (j < c_off2[l]) l--;
    int d = 2 * l + 1;
    int r = j - c_off2[l];
    int v = r / d, m = r - v * d;
    float acc = 0.f;
    #pragma unroll
    for (int f = 0; f < G_; f++) {
        const float* xr = d_x5 + (size_t)(b * G_ + f) * SO3 + c_off2[l];
        const float* pr = d_psi2 + f * SO3 + c_off2[l];
        for (int u = 0; u < d; u++) acc += xr[u * d + m] * pr[u * d + v];
    }
    out[t] = acc * (1.0f / sqrtf(8.0f * d));
}

// ---------------------------------------------------------------------------
// Host launcher
// ---------------------------------------------------------------------------
extern "C" void kernel_launch(void* const* d_in, const int* in_sizes, int n_in,
                              void* d_out, int out_size) {
    const float* fmap     = (const float*)d_in[0];
    const float* conv_w   = (const float*)d_in[1];
    const float* conv_b   = (const float*)d_in[2];
    const float* proj_w   = (const float*)d_in[3];
    const float* proj_Y   = (const float*)d_in[4];
    const float* fs_w     = (const float*)d_in[5];
    const float* fs_Y     = (const float*)d_in[6];
    const float* act_to   = (const float*)d_in[7];
    const float* act_from = (const float*)d_in[8];
    const float* so3_w    = (const float*)d_in[9];
    const float* so3_D    = (const float*)d_in[10];
    float* out = (float*)d_out;

    float *pP, *pPsi, *pW2c, *pPartD, *pPart6;
    bf16 *pADh, *pADl, *pW2th, *pW2tl, *pX4h, *pX4l, *pB5h, *pB5l;
    bf16 *pGh, *pGl, *pB6h, *pB6l;
    cudaGetSymbolAddress((void**)&pP,     d_P);
    cudaGetSymbolAddress((void**)&pPsi,   d_psi);
    cudaGetSymbolAddress((void**)&pW2c,   d_W2c);
    cudaGetSymbolAddress((void**)&pPartD, d_partD);
    cudaGetSymbolAddress((void**)&pPart6, d_part6);
    cudaGetSymbolAddress((void**)&pADh,   d_ADh);
    cudaGetSymbolAddress((void**)&pADl,   d_ADl);
    cudaGetSymbolAddress((void**)&pW2th,  d_W2th);
    cudaGetSymbolAddress((void**)&pW2tl,  d_W2tl);
    cudaGetSymbolAddress((void**)&pX4h,   d_x4h);
    cudaGetSymbolAddress((void**)&pX4l,   d_x4l);
    cudaGetSymbolAddress((void**)&pB5h,   d_bt5h);
    cudaGetSymbolAddress((void**)&pB5l,   d_bt5l);
    cudaGetSymbolAddress((void**)&pGh,    d_gacth);
    cudaGetSymbolAddress((void**)&pGl,    d_gactl);
    cudaGetSymbolAddress((void**)&pB6h,   d_bt6h);
    cudaGetSymbolAddress((void**)&pB6l,   d_bt6l);

    auto* kW2 = mmag_f<true,  true,  false, 64, false>;
    auto* kAD = mmag_f<false, true,  true,  64, true >;
    auto* kSD = mmag_p<false, false, true >;
    auto* kS5 = mmag_p<true,  true,  false>;
    auto* kS6 = mmag_p<false, false, false>;
    constexpr int SMP = 2 * 2 * 2 * 128 * 40 * 2;   // 81920 B
    cudaFuncSetAttribute(kSD, cudaFuncAttributeMaxDynamicSharedMemorySize, SMP);
    cudaFuncSetAttribute(kS5, cudaFuncAttributeMaxDynamicSharedMemorySize, SMP);
    cudaFuncSetAttribute(kS6, cudaFuncAttributeMaxDynamicSharedMemorySize, SMP);

    // small precomputes
    k_P   <<<(HW * S2 + 255) / 256, 256>>>(proj_w, proj_Y);
    k_q   <<<1, 64>>>();
    k_psi <<<(FIN * GI + 255) / 256, 256>>>(fs_w, fs_Y);
    k_bpsi<<<2, 256>>>(conv_b);
    k_psi2<<<(G_ * SO3 * 32 + 127) / 128, 128>>>(so3_w, so3_D);

    // operand transposes -> bf16 planes
    k_tpose<<<dim3(128, 15), dim3(32, 8)>>>(act_to,   pB5h, pB5l, SO3, NG, 480);
    k_tpose<<<dim3(16, 128), dim3(32, 8)>>>(act_from, pB6h, pB6l, NG, SO3, 4096);

    // W2c = RS512 * conv_w^T @ psi   (M=2048, N=392, K=512)
    kW2<<<dim3(7, 16, 1), 256>>>(conv_w, pPsi, pW2c, (bf16*)0, (bf16*)0,
                                 C_, GI, 448, FIN, GI, RS512, 16);
    k_w2t<<<(7 * 128 * C_ + 255) / 256, 256>>>();

    // AD planes: (fmap @ P)^T   (M=262144, N=49, K=49), OTRANS + packed planes
    kAD<<<dim3(1, 2048, 1), 256>>>(fmap, pP, (float*)0, pADh, pADl,
                                   HW, S2, (int)BC, HW, S2, 1.f, 2);

    // stageD: 49 batches (M=128, N=104(128), K=2048), split-K x4 -> partD
    kSD<<<dim3(1, 1, 196), 256, SMP>>>(pADh, pADl, pW2th, pW2tl,
        pPartD, (bf16*)0, (bf16*)0,
        C_, C_, 104, 104, 16, 512, 2,
        BC, (size_t)128 * C_, (size_t)128 * 104, (size_t)49 * 128 * 104);
    k_x4<<<(1024 * 512 + 255) / 256, 256>>>();

    // stage5: gact planes = relu(x4 @ act_to)  (M=1024, N=4096, K=480)
    kS5<<<dim3(32, 8, 1), 256, SMP>>>(pX4h, pX4l, pB5h, pB5l,
        (float*)0, pGh, pGl,
        512, 480, 4096, 4096, 15, 0, 0, 0, 0, 0, 0);

    // stage6: part6[z] = gact @ act_from  (M=1024, N=512, K=4096), split-K x8
    kS6<<<dim3(4, 8, 8), 256, SMP>>>(pGh, pGl, pB6h, pB6l,
        pPart6, (bf16*)0, (bf16*)0,
        4096, 4096, 512, 512, 16, 512, 3,
        0, 0, 0, (size_t)1024 * 512);
    k_red6<<<(1024 * SO3 + 255) / 256, 256>>>();

    // stage H
    stageH_kernel<<<(B_ * SO3 + 255) / 256, 256>>>(out);
}

// round 10
// speedup vs baseline: 3.9004x; 1.0169x over previous
#include <cuda_runtime.h>
#include <cuda_bf16.h>
#include <math.h>
#include <stdint.h>

typedef __nv_bfloat16 bf16;

// ---------------------------------------------------------------------------
// Problem constants
// ---------------------------------------------------------------------------
static constexpr int B_   = 128;
static constexpr int C_   = 2048;
static constexpr int HW   = 49;
static constexpr int FIN  = 512;
static constexpr int G_   = 8;
static constexpr int NP   = 192;
static constexpr int S2   = 49;
static constexpr int SO3  = 455;
static constexpr int NG   = 4000;
static constexpr int GI   = 392;                // G_*S2
static constexpr size_t BC = (size_t)B_ * C_;   // 262144

static constexpr float RS192 = 0.07216878364870323f;
static constexpr float RS512 = 0.04419417382415922f;

// ---------------------------------------------------------------------------
// Scratch (device globals; runtime allocation is forbidden)
// ---------------------------------------------------------------------------
__device__ float d_P[HW * S2];
__device__ float d_q[S2];
__device__ float d_psi[FIN * GI];
__device__ float d_bpsi[GI];
__device__ float d_psi2[G_ * SO3];
__device__ float d_W2c[C_ * 448];                    // [c][gi pad 448]

// hi/lo bf16 planes (pre-split operands for the pipelined GEMMs)
__device__ __align__(16) bf16 d_ADh[(size_t)49 * BC];   // [i][b*2048+c]
__device__ __align__(16) bf16 d_ADl[(size_t)49 * BC];
__device__ __align__(16) bf16 d_W2th[7 * 128 * C_];     // [l][j pad128][c]
__device__ __align__(16) bf16 d_W2tl[7 * 128 * C_];
__device__ __align__(16) bf16 d_x4h[1024 * 512];        // [b*8+g][so3 pad512]
__device__ __align__(16) bf16 d_x4l[1024 * 512];
__device__ __align__(16) bf16 d_bt5h[(size_t)4096 * 480]; // act_to^T planes
__device__ __align__(16) bf16 d_bt5l[(size_t)4096 * 480];
__device__ __align__(16) bf16 d_gacth[(size_t)1024 * 4096];
__device__ __align__(16) bf16 d_gactl[(size_t)1024 * 4096];
__device__ __align__(16) bf16 d_bt6h[(size_t)512 * 4096]; // act_from^T planes
__device__ __align__(16) bf16 d_bt6l[(size_t)512 * 4096];

__device__ float d_partD[(size_t)4 * 49 * 128 * 104];
__device__ float d_part6[(size_t)4 * 1024 * 512];
__device__ float d_x5[1024 * SO3];

__constant__ int c_off2[8] = {0, 1, 10, 35, 84, 165, 286, 455};
__constant__ int c_l_of_i[49] = {
    0, 1,1,1, 2,2,2,2,2, 3,3,3,3,3,3,3, 4,4,4,4,4,4,4,4,4,
    5,5,5,5,5,5,5,5,5,5,5, 6,6,6,6,6,6,6,6,6,6,6,6,6};

// ---------------------------------------------------------------------------
// helpers
// ---------------------------------------------------------------------------
__device__ __forceinline__ uint32_t smem_u32(const void* p) {
    uint32_t a;
    asm("{ .reg .u64 t; cvta.to.shared.u64 t, %1; cvt.u32.u64 %0, t; }"
        : "=r"(a) : "l"(p));
    return a;
}

__device__ __forceinline__ void ldsm4(uint32_t addr, uint32_t r[4]) {
    asm volatile("ldmatrix.sync.aligned.m8n8.x4.shared.b16 {%0,%1,%2,%3}, [%4];"
                 : "=r"(r[0]), "=r"(r[1]), "=r"(r[2]), "=r"(r[3]) : "r"(addr));
}

__device__ __forceinline__ void mma16816(float c[4], const uint32_t a[4],
                                         const uint32_t b[2]) {
    asm volatile(
        "mma.sync.aligned.m16n8k16.row.col.f32.bf16.bf16.f32 "
        "{%0,%1,%2,%3}, {%4,%5,%6,%7}, {%8,%9}, {%0,%1,%2,%3};"
        : "+f"(c[0]), "+f"(c[1]), "+f"(c[2]), "+f"(c[3])
        : "r"(a[0]), "r"(a[1]), "r"(a[2]), "r"(a[3]), "r"(b[0]), "r"(b[1]));
}

__device__ __forceinline__ void split2(float v, bf16& h, bf16& l) {
    h = __float2bfloat16(v);
    l = __float2bfloat16(v - __bfloat162float(h));
}

__device__ __forceinline__ uint32_t pack2(bf16 a, bf16 b) {
    return (uint32_t)__bfloat16_as_ushort(a) |
           ((uint32_t)__bfloat16_as_ushort(b) << 16);
}

// ---------------------------------------------------------------------------
// Engine A (fp32 inputs, split-on-load) — used for W2 and psi GEMMs.
// ---------------------------------------------------------------------------
template<bool ATRANS, bool BTRANS, int NT>
__global__ void __launch_bounds__(256) mmag_f(
    const float* __restrict__ A, const float* __restrict__ Bsrc,
    float* __restrict__ C,
    int lda, int ldb, int ldc, int Kreal, int Nreal, float alpha, int kchunks)
{
    constexpr int NT16 = NT / 16;
    __shared__ bf16 sA[2][128][40];
    __shared__ bf16 sB[2][NT][40];

    const int tid = threadIdx.x;
    const int r0 = blockIdx.y * 128;
    const int n0 = blockIdx.x * NT;
    const int lane = tid & 31, w = tid >> 5;
    const int wm = w & 3, wn = w >> 2;
    const int rA = wm * 32;
    const int nbase = wn * (NT / 2);

    float acc[2][NT16][4];
    #pragma unroll
    for (int mi = 0; mi < 2; mi++)
        #pragma unroll
        for (int ni = 0; ni < NT16; ni++)
            #pragma unroll
            for (int j = 0; j < 4; j++) acc[mi][ni][j] = 0.f;

    for (int ch = 0; ch < kchunks; ch++) {
        const int kc = ch * 32;
        __syncthreads();
        #pragma unroll
        for (int it = 0; it < 16; it++) {
            int idx = it * 256 + tid;
            int r, kk;
            if (ATRANS) { r = idx & 127; kk = idx >> 7; }
            else        { kk = idx & 31; r = idx >> 5;  }
            int gk = kc + kk;
            float v = 0.f;
            if (gk < Kreal)
                v = ATRANS ? A[(size_t)gk * lda + (r0 + r)]
                           : A[(size_t)(r0 + r) * lda + gk];
            split2(v, sA[0][r][kk], sA[1][r][kk]);
        }
        #pragma unroll
        for (int it = 0; it < NT / 8; it++) {
            int idx = it * 256 + tid;
            int n, kk;
            if (BTRANS) { n = idx & (NT - 1); kk = idx >> (NT == 128 ? 7 : 6); }
            else        { kk = idx & 31;      n = idx >> 5; }
            int gk = kc + kk, gn = n0 + n;
            float v = 0.f;
            if (gk < Kreal && gn < Nreal)
                v = BTRANS ? Bsrc[(size_t)gk * ldb + gn]
                           : Bsrc[(size_t)gn * ldb + gk];
            split2(v, sB[0][n][kk], sB[1][n][kk]);
        }
        __syncthreads();
        #pragma unroll
        for (int kk = 0; kk < 32; kk += 16) {
            uint32_t aH[2][4], aL[2][4];
            const int arow = rA + (lane & 7) + ((lane >> 3) & 1) * 8;
            const int akc  = kk + (lane >> 4) * 8;
            #pragma unroll
            for (int mi = 0; mi < 2; mi++) {
                ldsm4(smem_u32(&sA[0][arow + mi * 16][akc]), aH[mi]);
                ldsm4(smem_u32(&sA[1][arow + mi * 16][akc]), aL[mi]);
            }
            #pragma unroll
            for (int np = 0; np < NT16 / 2; np++) {
                uint32_t bH[4], bL[4];
                const int brow = nbase + np * 16 + (lane >> 4) * 8 + (lane & 7);
                const int bkc  = kk + ((lane >> 3) & 1) * 8;
                ldsm4(smem_u32(&sB[0][brow][bkc]), bH);
                ldsm4(smem_u32(&sB[1][brow][bkc]), bL);
                #pragma unroll
                for (int mi = 0; mi < 2; mi++) {
                    #pragma unroll
                    for (int h = 0; h < 2; h++) {
                        int ni = 2 * np + h;
                        mma16816(acc[mi][ni], aH[mi], &bH[2 * h]);
                        mma16816(acc[mi][ni], aH[mi], &bL[2 * h]);
                        mma16816(acc[mi][ni], aL[mi], &bH[2 * h]);
                    }
                }
            }
        }
    }

    const int g2 = lane >> 2, tg = lane & 3;
    #pragma unroll
    for (int mi = 0; mi < 2; mi++) {
        #pragma unroll
        for (int ni = 0; ni < NT16; ni++) {
            int row = r0 + rA + mi * 16 + g2;
            int col = n0 + nbase + ni * 8 + tg * 2;
            #pragma unroll
            for (int j = 0; j < 4; j++) {
                int rr = row + (j >> 1) * 8;
                int nn = col + (j & 1);
                if (nn < Nreal)
                    C[(size_t)rr * ldc + nn] = alpha * acc[mi][ni][j];
            }
        }
    }
}

// ---------------------------------------------------------------------------
// Specialized AD kernel: AD[i][bc] = sum_hw fmap[bc][hw] * P[hw][i]
// (engine-A math, NT=64, K=49, 2 chunks) with SMEM-staged COALESCED
// transposed plane stores. grid.x = 2048 (128 bc rows per CTA).
// ---------------------------------------------------------------------------
__global__ void __launch_bounds__(256) kAD_kernel(
    const float* __restrict__ A, bf16* __restrict__ Ch, bf16* __restrict__ Cl)
{
    __shared__ __align__(16) char smr[30720];
    bf16 (*sA)[128][40] = reinterpret_cast<bf16(*)[128][40]>(smr);
    bf16 (*sB)[64][40]  = reinterpret_cast<bf16(*)[64][40]>(smr + 20480);

    const int tid = threadIdx.x;
    const int r0 = blockIdx.x * 128;
    const int lane = tid & 31, w = tid >> 5;
    const int rA = (w & 3) * 32;
    const int nbase = (w >> 2) * 32;

    float acc[2][4][4];
    #pragma unroll
    for (int mi = 0; mi < 2; mi++)
        #pragma unroll
        for (int ni = 0; ni < 4; ni++)
            #pragma unroll
            for (int j = 0; j < 4; j++) acc[mi][ni][j] = 0.f;

    for (int ch = 0; ch < 2; ch++) {
        const int kc = ch * 32;
        __syncthreads();
        #pragma unroll
        for (int it = 0; it < 16; it++) {
            int idx = it * 256 + tid;
            int kk = idx & 31, r = idx >> 5;
            int gk = kc + kk;
            float v = (gk < HW) ? A[(size_t)(r0 + r) * HW + gk] : 0.f;
            split2(v, sA[0][r][kk], sA[1][r][kk]);
        }
        #pragma unroll
        for (int it = 0; it < 8; it++) {
            int idx = it * 256 + tid;
            int n = idx & 63, kk = idx >> 6;
            int gk = kc + kk;
            float v = (gk < HW && n < S2) ? d_P[gk * S2 + n] : 0.f;
            split2(v, sB[0][n][kk], sB[1][n][kk]);
        }
        __syncthreads();
        #pragma unroll
        for (int kk = 0; kk < 32; kk += 16) {
            uint32_t aH[2][4], aL[2][4];
            const int arow = rA + (lane & 7) + ((lane >> 3) & 1) * 8;
            const int akc  = kk + (lane >> 4) * 8;
            #pragma unroll
            for (int mi = 0; mi < 2; mi++) {
                ldsm4(smem_u32(&sA[0][arow + mi * 16][akc]), aH[mi]);
                ldsm4(smem_u32(&sA[1][arow + mi * 16][akc]), aL[mi]);
            }
            #pragma unroll
            for (int np = 0; np < 2; np++) {
                uint32_t bH[4], bL[4];
                const int brow = nbase + np * 16 + (lane >> 4) * 8 + (lane & 7);
                const int bkc  = kk + ((lane >> 3) & 1) * 8;
                ldsm4(smem_u32(&sB[0][brow][bkc]), bH);
                ldsm4(smem_u32(&sB[1][brow][bkc]), bL);
                #pragma unroll
                for (int mi = 0; mi < 2; mi++) {
                    #pragma unroll
                    for (int h = 0; h < 2; h++) {
                        int ni = 2 * np + h;
                        mma16816(acc[mi][ni], aH[mi], &bH[2 * h]);
                        mma16816(acc[mi][ni], aH[mi], &bL[2 * h]);
                        mma16816(acc[mi][ni], aL[mi], &bH[2 * h]);
                    }
                }
            }
        }
    }

    // stage into SMEM transposed, then coalesced plane stores
    __syncthreads();
    bf16 (*sH)[128] = reinterpret_cast<bf16(*)[128]>(smr);          // [49][128]
    bf16 (*sL)[128] = reinterpret_cast<bf16(*)[128]>(smr + 12800);
    const int g2 = lane >> 2, tg = lane & 3;
    #pragma unroll
    for (int mi = 0; mi < 2; mi++) {
        #pragma unroll
        for (int ni = 0; ni < 4; ni++) {
            int rowl = rA + mi * 16 + g2;
            int col = nbase + ni * 8 + tg * 2;
            #pragma unroll
            for (int j = 0; j < 4; j++) {
                int rr = rowl + (j >> 1) * 8;
                int nn = col + (j & 1);
                if (nn < S2) {
                    bf16 h, l;
                    split2(acc[mi][ni][j], h, l);
                    sH[nn][rr] = h;
                    sL[nn][rr] = l;
                }
            }
        }
    }
    __syncthreads();
    for (int idx = tid; idx < S2 * 128; idx += 256) {
        int i = idx >> 7, r = idx & 127;
        size_t o = (size_t)i * BC + r0 + r;
        Ch[o] = sH[i][r];
        Cl[o] = sL[i][r];
    }
}

// ---------------------------------------------------------------------------
// Engine B (pre-split bf16 planes, cp.async double-buffered) — stageD/5/6.
// ---------------------------------------------------------------------------
template<bool RELU, bool PACKOUT, bool LSEL>
__global__ void __launch_bounds__(256) mmag_p(
    const bf16* __restrict__ Ah, const bf16* __restrict__ Al,
    const bf16* __restrict__ Bh, const bf16* __restrict__ Bl,
    float* __restrict__ C, bf16* __restrict__ Ch, bf16* __restrict__ Cl,
    int lda, int ldb, int ldc, int Nreal,
    int kchunks, int kstride, int zdiv,
    size_t astride, size_t bstride, size_t cstride, size_t cstride2)
{
    extern __shared__ bf16 S[];   // sA[2buf][2pl][128][40] then sB same: 81920 B
    const int tid = threadIdx.x;
    const int z = blockIdx.z;
    const int batch = z >> zdiv;
    const int sub = z - (batch << zdiv);
    const bf16* Aph = Ah + (size_t)batch * astride;
    const bf16* Apl = Al + (size_t)batch * astride;
    const size_t boff = (LSEL ? (size_t)c_l_of_i[batch] : (size_t)batch) * bstride;
    const bf16* Bph = Bh + boff;
    const bf16* Bpl = Bl + boff;
    float* Cp = C + (size_t)batch * cstride + (size_t)sub * cstride2;
    const int kbeg = sub * kstride;
    const int r0 = blockIdx.y * 128;
    const int n0 = blockIdx.x * 128;
    const int lane = tid & 31, w = tid >> 5;
    const int rA = (w & 3) * 32;
    const int nbase = (w >> 2) * 64;
    const uint32_t sbase = smem_u32(S);
    constexpr uint32_t SBOFF = 2 * 2 * 128 * 40 * 2;   // bytes

    float acc[2][8][4];
    #pragma unroll
    for (int mi = 0; mi < 2; mi++)
        #pragma unroll
        for (int ni = 0; ni < 8; ni++)
            #pragma unroll
            for (int j = 0; j < 4; j++) acc[mi][ni][j] = 0.f;

    auto copyin = [&](int buf, int kc) {
        #pragma unroll
        for (int it = 0; it < 8; it++) {
            int idx = it * 256 + tid;
            int q = idx & 7, r = (idx >> 3) & 127, p = idx >> 10;
            const bf16* g = (p ? Apl : Aph) + (size_t)(r0 + r) * lda + kc + q * 4;
            uint32_t d = sbase + (((buf * 2 + p) * 128 + r) * 40 + q * 4) * 2;
            asm volatile("cp.async.ca.shared.global [%0], [%1], 8;"
                         :: "r"(d), "l"(g));
        }
        #pragma unroll
        for (int it = 0; it < 8; it++) {
            int idx = it * 256 + tid;
            int q = idx & 7, r = (idx >> 3) & 127, p = idx >> 10;
            const bf16* g = (p ? Bpl : Bph) + (size_t)(n0 + r) * ldb + kc + q * 4;
            uint32_t d = sbase + SBOFF + (((buf * 2 + p) * 128 + r) * 40 + q * 4) * 2;
            asm volatile("cp.async.ca.shared.global [%0], [%1], 8;"
                         :: "r"(d), "l"(g));
        }
        asm volatile("cp.async.commit_group;" ::: "memory");
    };

    int buf = 0;
    copyin(0, kbeg);

    for (int ch = 0; ch < kchunks; ch++) {
        if (ch + 1 < kchunks) {
            copyin(buf ^ 1, kbeg + (ch + 1) * 32);
            asm volatile("cp.async.wait_group 1;" ::: "memory");
        } else {
            asm volatile("cp.async.wait_group 0;" ::: "memory");
        }
        __syncthreads();

        #pragma unroll
        for (int kk = 0; kk < 32; kk += 16) {
            uint32_t aH[2][4], aL[2][4];
            const int arow = rA + (lane & 7) + ((lane >> 3) & 1) * 8;
            const int akc  = kk + (lane >> 4) * 8;
            #pragma unroll
            for (int mi = 0; mi < 2; mi++) {
                uint32_t a0 = sbase + (((buf * 2 + 0) * 128 + arow + mi * 16) * 40 + akc) * 2;
                uint32_t a1 = sbase + (((buf * 2 + 1) * 128 + arow + mi * 16) * 40 + akc) * 2;
                ldsm4(a0, aH[mi]);
                ldsm4(a1, aL[mi]);
            }
            #pragma unroll
            for (int np = 0; np < 4; np++) {
                uint32_t bH[4], bL[4];
                const int brow = nbase + np * 16 + (lane >> 4) * 8 + (lane & 7);
                const int bkc  = kk + ((lane >> 3) & 1) * 8;
                uint32_t b0 = sbase + SBOFF + (((buf * 2 + 0) * 128 + brow) * 40 + bkc) * 2;
                uint32_t b1 = sbase + SBOFF + (((buf * 2 + 1) * 128 + brow) * 40 + bkc) * 2;
                ldsm4(b0, bH);
                ldsm4(b1, bL);
                #pragma unroll
                for (int mi = 0; mi < 2; mi++) {
                    #pragma unroll
                    for (int h = 0; h < 2; h++) {
                        int ni = 2 * np + h;
                        mma16816(acc[mi][ni], aH[mi], &bH[2 * h]);
                        mma16816(acc[mi][ni], aH[mi], &bL[2 * h]);
                        mma16816(acc[mi][ni], aL[mi], &bH[2 * h]);
                    }
                }
            }
        }
        __syncthreads();
        buf ^= 1;
    }

    const int g2 = lane >> 2, tg = lane & 3;
    #pragma unroll
    for (int mi = 0; mi < 2; mi++) {
        #pragma unroll
        for (int ni = 0; ni < 8; ni++) {
            int row = r0 + rA + mi * 16 + g2;
            int col = n0 + nbase + ni * 8 + tg * 2;
            float v[4];
            #pragma unroll
            for (int j = 0; j < 4; j++) {
                v[j] = acc[mi][ni][j];
                if (RELU) v[j] = fmaxf(v[j], 0.f);
            }
            if (PACKOUT) {
                #pragma unroll
                for (int h = 0; h < 2; h++) {
                    int rr = row + h * 8;
                    bf16 h0, l0, h1, l1;
                    split2(v[2 * h + 0], h0, l0);
                    split2(v[2 * h + 1], h1, l1);
                    *(uint32_t*)&Ch[(size_t)rr * ldc + col] = pack2(h0, h1);
                    *(uint32_t*)&Cl[(size_t)rr * ldc + col] = pack2(l0, l1);
                }
            } else {
                #pragma unroll
                for (int j = 0; j < 4; j++) {
                    int rr = row + (j >> 1) * 8;
                    int nn = col + (j & 1);
                    if (nn < Nreal) Cp[(size_t)rr * ldc + nn] = v[j];
                }
            }
        }
    }
}

// ---------------------------------------------------------------------------
// Small kernels
// ---------------------------------------------------------------------------
// P and q in one block
__global__ void k_Pq(const float* __restrict__ proj_w, const float* __restrict__ proj_Y) {
    const int tid = threadIdx.x;
    for (int t = tid; t < HW * S2; t += 256) {
        int hw = t / S2, i = t % S2;
        const float* wr = proj_w + hw * NP;
        float acc = 0.f;
        #pragma unroll 8
        for (int n = 0; n < NP; n++) acc += wr[n] * proj_Y[n * S2 + i];
        d_P[t] = acc * RS192;
    }
    __syncthreads();
    if (tid < S2) {
        float a = 0.f;
        for (int hw = 0; hw < HW; hw++) a += d_P[hw * S2 + tid];
        d_q[tid] = a;
    }
}

// block: 32 outputs, 8 warps x 64 f each, coalesced psi loads, smem reduce
__global__ void k_bpsi(const float* __restrict__ conv_b) {
    __shared__ float part[8][33];
    const int lane = threadIdx.x & 31, w = threadIdx.x >> 5;
    const int t = blockIdx.x * 32 + lane;
    float acc = 0.f;
    if (t < GI) {
        #pragma unroll 8
        for (int ff = 0; ff < 64; ff++) {
            int f = w * 64 + ff;
            acc += conv_b[f] * d_psi[f * GI + t];
        }
    }
    part[w][lane] = acc;
    __syncthreads();
    if (w == 0 && t < GI) {
        float s = 0.f;
        #pragma unroll
        for (int j = 0; j < 8; j++) s += part[j][lane];
        d_bpsi[t] = s * RS512;
    }
}

__global__ void k_psi2(const float* __restrict__ so3_w, const float* __restrict__ so3_D) {
    int w = (blockIdx.x * blockDim.x + threadIdx.x) >> 5;
    int lane = threadIdx.x & 31;
    if (w >= G_ * SO3) return;
    int f = w / SO3, i = w % SO3;
    float acc = 0.f;
    for (int n = lane; n < NP; n += 32) acc += so3_w[f * NP + n] * so3_D[n * SO3 + i];
    #pragma unroll
    for (int o = 16; o; o >>= 1) acc += __shfl_xor_sync(0xFFFFFFFFu, acc, o);
    if (lane == 0) d_psi2[w] = acc * RS192;
}

// tiled transpose + hi/lo split: out[n][k] = in[k][n], zero-padded
__global__ void k_tpose(const float* __restrict__ in, bf16* __restrict__ oh,
                        bf16* __restrict__ ol, int inR, int inC, int ldo) {
    __shared__ float tl[32][33];
    int n0 = blockIdx.x * 32, k0 = blockIdx.y * 32;
    #pragma unroll
    for (int j = 0; j < 4; j++) {
        int k = k0 + threadIdx.y + j * 8, n = n0 + threadIdx.x;
        tl[threadIdx.y + j * 8][threadIdx.x] =
            (k < inR && n < inC) ? in[(size_t)k * inC + n] : 0.f;
    }
    __syncthreads();
    #pragma unroll
    for (int j = 0; j < 4; j++) {
        int n = n0 + threadIdx.y + j * 8, k = k0 + threadIdx.x;
        bf16 h, l;
        split2(tl[threadIdx.x][threadIdx.y + j * 8], h, l);
        oh[(size_t)n * ldo + k] = h;
        ol[(size_t)n * ldo + k] = l;
    }
}

// W2c [c][gi pad448] -> planes [l][j pad128][c]
__global__ void k_w2t() {
    int t = blockIdx.x * blockDim.x + threadIdx.x;
    if (t >= 7 * 128 * C_) return;
    int l = t / (128 * C_);
    int r = t - l * 128 * C_;
    int j = r / C_, c = r - j * C_;
    int d = 2 * l + 1;
    float v = 0.f;
    if (j < 8 * d) {
        int g = j / d, u = j - g * d;
        v = d_W2c[(size_t)c * 448 + g * S2 + l * l + u];
    }
    bf16 h, lo;
    split2(v, h, lo);
    d_W2th[t] = h;
    d_W2tl[t] = lo;
}

// partD (4 k-slabs) + bias -> x4 planes [1024][512] (zero pad cols >= 455)
__global__ void k_x4() {
    int t = blockIdx.x * blockDim.x + threadIdx.x;
    if (t >= 1024 * 512) return;
    int row = t >> 9, col = t & 511;
    int b = row >> 3, g = row & 7;
    float v = 0.f;
    if (col < SO3) {
        int l = 6;
        while (col < c_off2[l]) l--;
        int d = 2 * l + 1, r = col - c_off2[l];
        int u = r / d, m = r - u * d, i = l * l + m;
        size_t o = (size_t)i * 128 * 104 + (size_t)b * 104 + g * d + u;
        float s = 0.f;
        #pragma unroll
        for (int zz = 0; zz < 4; zz++)
            s += d_partD[o + (size_t)zz * 49 * 128 * 104];
        v = s + d_bpsi[g * S2 + l * l + u] * d_q[l * l + m];
    }
    bf16 h, lo;
    split2(v, h, lo);
    d_x4h[t] = h;
    d_x4l[t] = lo;
}

__global__ void k_red6() {
    int t = blockIdx.x * blockDim.x + threadIdx.x;
    if (t >= 1024 * SO3) return;
    int row = t / SO3, col = t - row * SO3;
    float s = 0.f;
    #pragma unroll
    for (int zz = 0; zz < 4; zz++)
        s += d_part6[(size_t)zz * 1024 * 512 + (size_t)row * 512 + col];
    d_x5[t] = s;
}

__global__ void stageH_kernel(float* __restrict__ out) {
    int t = blockIdx.x * blockDim.x + threadIdx.x;
    if (t >= B_ * SO3) return;
    int b = t / SO3, j = t - b * SO3;
    int l = 6;
    while (j < c_off2[l]) l--;
    int d = 2 * l + 1;
    int r = j - c_off2[l];
    int v = r / d, m = r - v * d;
    float acc = 0.f;
    #pragma unroll
    for (int f = 0; f < G_; f++) {
        const float* xr = d_x5 + (size_t)(b * G_ + f) * SO3 + c_off2[l];
        const float* pr = d_psi2 + f * SO3 + c_off2[l];
        for (int u = 0; u < d; u++) acc += xr[u * d + m] * pr[u * d + v];
    }
    out[t] = acc * (1.0f / sqrtf(8.0f * d));
}

// ---------------------------------------------------------------------------
// Host launcher
// ---------------------------------------------------------------------------
extern "C" void kernel_launch(void* const* d_in, const int* in_sizes, int n_in,
                              void* d_out, int out_size) {
    const float* fmap     = (const float*)d_in[0];
    const float* conv_w   = (const float*)d_in[1];
    const float* conv_b   = (const float*)d_in[2];
    const float* proj_w   = (const float*)d_in[3];
    const float* proj_Y   = (const float*)d_in[4];
    const float* fs_w     = (const float*)d_in[5];
    const float* fs_Y     = (const float*)d_in[6];
    const float* act_to   = (const float*)d_in[7];
    const float* act_from = (const float*)d_in[8];
    const float* so3_w    = (const float*)d_in[9];
    const float* so3_D    = (const float*)d_in[10];
    float* out = (float*)d_out;

    float *pPsi, *pW2c, *pPartD, *pPart6;
    bf16 *pADh, *pADl, *pW2th, *pW2tl, *pX4h, *pX4l, *pB5h, *pB5l;
    bf16 *pGh, *pGl, *pB6h, *pB6l;
    cudaGetSymbolAddress((void**)&pPsi,   d_psi);
    cudaGetSymbolAddress((void**)&pW2c,   d_W2c);
    cudaGetSymbolAddress((void**)&pPartD, d_partD);
    cudaGetSymbolAddress((void**)&pPart6, d_part6);
    cudaGetSymbolAddress((void**)&pADh,   d_ADh);
    cudaGetSymbolAddress((void**)&pADl,   d_ADl);
    cudaGetSymbolAddress((void**)&pW2th,  d_W2th);
    cudaGetSymbolAddress((void**)&pW2tl,  d_W2tl);
    cudaGetSymbolAddress((void**)&pX4h,   d_x4h);
    cudaGetSymbolAddress((void**)&pX4l,   d_x4l);
    cudaGetSymbolAddress((void**)&pB5h,   d_bt5h);
    cudaGetSymbolAddress((void**)&pB5l,   d_bt5l);
    cudaGetSymbolAddress((void**)&pGh,    d_gacth);
    cudaGetSymbolAddress((void**)&pGl,    d_gactl);
    cudaGetSymbolAddress((void**)&pB6h,   d_bt6h);
    cudaGetSymbolAddress((void**)&pB6l,   d_bt6l);

    auto* kW2  = mmag_f<true,  true,  64>;
    auto* kPsi = mmag_f<false, true,  64>;
    auto* kSD = mmag_p<false, false, true >;
    auto* kS5 = mmag_p<true,  true,  false>;
    auto* kS6 = mmag_p<false, false, false>;
    constexpr int SMP = 2 * 2 * 2 * 128 * 40 * 2;   // 81920 B
    cudaFuncSetAttribute(kSD, cudaFuncAttributeMaxDynamicSharedMemorySize, SMP);
    cudaFuncSetAttribute(kS5, cudaFuncAttributeMaxDynamicSharedMemorySize, SMP);
    cudaFuncSetAttribute(kS6, cudaFuncAttributeMaxDynamicSharedMemorySize, SMP);

    // small precomputes
    k_Pq  <<<1, 256>>>(proj_w, proj_Y);
    // psi = RS192 * fs_w @ fs_Y   (M=4096, N=49, K=192) via engine A
    kPsi<<<dim3(1, 32, 1), 256>>>(fs_w, fs_Y, pPsi, NP, S2, S2, NP, S2, RS192, 6);
    k_bpsi<<<(GI + 31) / 32, 256>>>(conv_b);
    k_psi2<<<(G_ * SO3 * 32 + 127) / 128, 128>>>(so3_w, so3_D);

    // operand transposes -> bf16 planes
    k_tpose<<<dim3(128, 15), dim3(32, 8)>>>(act_to,   pB5h, pB5l, SO3, NG, 480);
    k_tpose<<<dim3(16, 128), dim3(32, 8)>>>(act_from, pB6h, pB6l, NG, SO3, 4096);

    // W2c = RS512 * conv_w^T @ psi   (M=2048, N=392, K=512)
    kW2<<<dim3(7, 16, 1), 256>>>(conv_w, pPsi, pW2c, C_, GI, 448, FIN, GI, RS512, 16);
    k_w2t<<<(7 * 128 * C_ + 255) / 256, 256>>>();

    // AD planes: (fmap @ P)^T  (M=262144, N=49, K=49), staged coalesced stores
    kAD_kernel<<<2048, 256>>>(fmap, pADh, pADl);

    // stageD: 49 batches (M=128, N=104(128), K=2048), split-K x4 -> partD
    kSD<<<dim3(1, 1, 196), 256, SMP>>>(pADh, pADl, pW2th, pW2tl,
        pPartD, (bf16*)0, (bf16*)0,
        C_, C_, 104, 104, 16, 512, 2,
        BC, (size_t)128 * C_, (size_t)128 * 104, (size_t)49 * 128 * 104);
    k_x4<<<(1024 * 512 + 255) / 256, 256>>>();

    // stage5: gact planes = relu(x4 @ act_to)  (M=1024, N=4096, K=480)
    kS5<<<dim3(32, 8, 1), 256, SMP>>>(pX4h, pX4l, pB5h, pB5l,
        (float*)0, pGh, pGl,
        512, 480, 4096, 4096, 15, 0, 0, 0, 0, 0, 0);

    // stage6: part6[z] = gact @ act_from  (M=1024, N=512, K=4096), split-K x4
    kS6<<<dim3(4, 8, 4), 256, SMP>>>(pGh, pGl, pB6h, pB6l,
        pPart6, (bf16*)0, (bf16*)0,
        4096, 4096, 512, 512, 32, 1024, 2,
        0, 0, 0, (size_t)1024 * 512);
    k_red6<<<(1024 * SO3 + 255) / 256, 256>>>();

    // stage H
    stageH_kernel<<<(B_ * SO3 + 255) / 256, 256>>>(out);
}

// round 12
// speedup vs baseline: 3.9678x; 1.0173x over previous
#include <cuda_runtime.h>
#include <cuda_bf16.h>
#include <math.h>
#include <stdint.h>

typedef __nv_bfloat16 bf16;

// ---------------------------------------------------------------------------
// Problem constants
// ---------------------------------------------------------------------------
static constexpr int B_   = 128;
static constexpr int C_   = 2048;
static constexpr int HW   = 49;
static constexpr int FIN  = 512;
static constexpr int G_   = 8;
static constexpr int NP   = 192;
static constexpr int S2   = 49;
static constexpr int SO3  = 455;
static constexpr int NG   = 4000;
static constexpr int GI   = 392;                // G_*S2
static constexpr size_t BC = (size_t)B_ * C_;   // 262144

static constexpr float RS192 = 0.07216878364870323f;
static constexpr float RS512 = 0.04419417382415922f;

// ---------------------------------------------------------------------------
// Scratch (device globals; runtime allocation is forbidden)
// ---------------------------------------------------------------------------
__device__ float d_P[HW * S2];
__device__ float d_q[S2];
__device__ float d_psi[FIN * GI];
__device__ float d_bpsi[GI];
__device__ float d_psi2[G_ * SO3];
__device__ float d_W2c[C_ * 448];                    // [c][gi pad 448]

// hi/lo bf16 planes (pre-split operands for the pipelined GEMMs)
__device__ __align__(16) bf16 d_ADh[(size_t)49 * BC];   // [i][b*2048+c]
__device__ __align__(16) bf16 d_ADl[(size_t)49 * BC];
__device__ __align__(16) bf16 d_W2th[7 * 128 * C_];     // [l][j pad128][c]
__device__ __align__(16) bf16 d_W2tl[7 * 128 * C_];
__device__ __align__(16) bf16 d_x4h[1024 * 512];        // [b*8+g][so3 pad512]
__device__ __align__(16) bf16 d_x4l[1024 * 512];
__device__ __align__(16) bf16 d_bt5h[(size_t)4096 * 480]; // act_to^T planes
__device__ __align__(16) bf16 d_bt5l[(size_t)4096 * 480];
__device__ __align__(16) bf16 d_gacth[(size_t)1024 * 4096];
__device__ __align__(16) bf16 d_gactl[(size_t)1024 * 4096];
__device__ __align__(16) bf16 d_bt6h[(size_t)512 * 4096]; // act_from^T planes
__device__ __align__(16) bf16 d_bt6l[(size_t)512 * 4096];

__device__ float d_partD[(size_t)8 * 49 * 128 * 104];
__device__ float d_part6[(size_t)8 * 1024 * 512];
__device__ float d_x5[1024 * SO3];

__constant__ int c_off2[8] = {0, 1, 10, 35, 84, 165, 286, 455};
__constant__ int c_l_of_i[49] = {
    0, 1,1,1, 2,2,2,2,2, 3,3,3,3,3,3,3, 4,4,4,4,4,4,4,4,4,
    5,5,5,5,5,5,5,5,5,5,5, 6,6,6,6,6,6,6,6,6,6,6,6,6};

// ---------------------------------------------------------------------------
// helpers
// ---------------------------------------------------------------------------
__device__ __forceinline__ uint32_t smem_u32(const void* p) {
    uint32_t a;
    asm("{ .reg .u64 t; cvta.to.shared.u64 t, %1; cvt.u32.u64 %0, t; }"
        : "=r"(a) : "l"(p));
    return a;
}

__device__ __forceinline__ void ldsm4(uint32_t addr, uint32_t r[4]) {
    asm volatile("ldmatrix.sync.aligned.m8n8.x4.shared.b16 {%0,%1,%2,%3}, [%4];"
                 : "=r"(r[0]), "=r"(r[1]), "=r"(r[2]), "=r"(r[3]) : "r"(addr));
}

__device__ __forceinline__ void mma16816(float c[4], const uint32_t a[4],
                                         const uint32_t b[2]) {
    asm volatile(
        "mma.sync.aligned.m16n8k16.row.col.f32.bf16.bf16.f32 "
        "{%0,%1,%2,%3}, {%4,%5,%6,%7}, {%8,%9}, {%0,%1,%2,%3};"
        : "+f"(c[0]), "+f"(c[1]), "+f"(c[2]), "+f"(c[3])
        : "r"(a[0]), "r"(a[1]), "r"(a[2]), "r"(a[3]), "r"(b[0]), "r"(b[1]));
}

__device__ __forceinline__ void split2(float v, bf16& h, bf16& l) {
    h = __float2bfloat16(v);
    l = __float2bfloat16(v - __bfloat162float(h));
}

__device__ __forceinline__ uint32_t pack2(bf16 a, bf16 b) {
    return (uint32_t)__bfloat16_as_ushort(a) |
           ((uint32_t)__bfloat16_as_ushort(b) << 16);
}

// ---------------------------------------------------------------------------
// Engine A (fp32 inputs, split-on-load) — used for W2 and psi GEMMs.
// ---------------------------------------------------------------------------
template<bool ATRANS, bool BTRANS, int NT>
__global__ void __launch_bounds__(256) mmag_f(
    const float* __restrict__ A, const float* __restrict__ Bsrc,
    float* __restrict__ C,
    int lda, int ldb, int ldc, int Kreal, int Nreal, float alpha, int kchunks)
{
    constexpr int NT16 = NT / 16;
    __shared__ bf16 sA[2][128][40];
    __shared__ bf16 sB[2][NT][40];

    const int tid = threadIdx.x;
    const int r0 = blockIdx.y * 128;
    const int n0 = blockIdx.x * NT;
    const int lane = tid & 31, w = tid >> 5;
    const int wm = w & 3, wn = w >> 2;
    const int rA = wm * 32;
    const int nbase = wn * (NT / 2);

    float acc[2][NT16][4];
    #pragma unroll
    for (int mi = 0; mi < 2; mi++)
        #pragma unroll
        for (int ni = 0; ni < NT16; ni++)
            #pragma unroll
            for (int j = 0; j < 4; j++) acc[mi][ni][j] = 0.f;

    for (int ch = 0; ch < kchunks; ch++) {
        const int kc = ch * 32;
        __syncthreads();
        #pragma unroll
        for (int it = 0; it < 16; it++) {
            int idx = it * 256 + tid;
            int r, kk;
            if (ATRANS) { r = idx & 127; kk = idx >> 7; }
            else        { kk = idx & 31; r = idx >> 5;  }
            int gk = kc + kk;
            float v = 0.f;
            if (gk < Kreal)
                v = ATRANS ? A[(size_t)gk * lda + (r0 + r)]
                           : A[(size_t)(r0 + r) * lda + gk];
            split2(v, sA[0][r][kk], sA[1][r][kk]);
        }
        #pragma unroll
        for (int it = 0; it < NT / 8; it++) {
            int idx = it * 256 + tid;
            int n, kk;
            if (BTRANS) { n = idx & (NT - 1); kk = idx >> (NT == 128 ? 7 : 6); }
            else        { kk = idx & 31;      n = idx >> 5; }
            int gk = kc + kk, gn = n0 + n;
            float v = 0.f;
            if (gk < Kreal && gn < Nreal)
                v = BTRANS ? Bsrc[(size_t)gk * ldb + gn]
                           : Bsrc[(size_t)gn * ldb + gk];
            split2(v, sB[0][n][kk], sB[1][n][kk]);
        }
        __syncthreads();
        #pragma unroll
        for (int kk = 0; kk < 32; kk += 16) {
            uint32_t aH[2][4], aL[2][4];
            const int arow = rA + (lane & 7) + ((lane >> 3) & 1) * 8;
            const int akc  = kk + (lane >> 4) * 8;
            #pragma unroll
            for (int mi = 0; mi < 2; mi++) {
                ldsm4(smem_u32(&sA[0][arow + mi * 16][akc]), aH[mi]);
                ldsm4(smem_u32(&sA[1][arow + mi * 16][akc]), aL[mi]);
            }
            #pragma unroll
            for (int np = 0; np < NT16 / 2; np++) {
                uint32_t bH[4], bL[4];
                const int brow = nbase + np * 16 + (lane >> 4) * 8 + (lane & 7);
                const int bkc  = kk + ((lane >> 3) & 1) * 8;
                ldsm4(smem_u32(&sB[0][brow][bkc]), bH);
                ldsm4(smem_u32(&sB[1][brow][bkc]), bL);
                #pragma unroll
                for (int mi = 0; mi < 2; mi++) {
                    #pragma unroll
                    for (int h = 0; h < 2; h++) {
                        int ni = 2 * np + h;
                        mma16816(acc[mi][ni], aH[mi], &bH[2 * h]);
                        mma16816(acc[mi][ni], aH[mi], &bL[2 * h]);
                        mma16816(acc[mi][ni], aL[mi], &bH[2 * h]);
                    }
                }
            }
        }
    }

    const int g2 = lane >> 2, tg = lane & 3;
    #pragma unroll
    for (int mi = 0; mi < 2; mi++) {
        #pragma unroll
        for (int ni = 0; ni < NT16; ni++) {
            int row = r0 + rA + mi * 16 + g2;
            int col = n0 + nbase + ni * 8 + tg * 2;
            #pragma unroll
            for (int j = 0; j < 4; j++) {
                int rr = row + (j >> 1) * 8;
                int nn = col + (j & 1);
                if (nn < Nreal)
                    C[(size_t)rr * ldc + nn] = alpha * acc[mi][ni][j];
            }
        }
    }
}

// ---------------------------------------------------------------------------
// Specialized AD kernel: AD[i][bc] = sum_hw fmap[bc][hw] * P[hw][i]
// SMEM-staged coalesced transposed plane stores. grid.x = 2048.
// ---------------------------------------------------------------------------
__global__ void __launch_bounds__(256) kAD_kernel(
    const float* __restrict__ A, bf16* __restrict__ Ch, bf16* __restrict__ Cl)
{
    __shared__ __align__(16) char smr[30720];
    bf16 (*sA)[128][40] = reinterpret_cast<bf16(*)[128][40]>(smr);
    bf16 (*sB)[64][40]  = reinterpret_cast<bf16(*)[64][40]>(smr + 20480);

    const int tid = threadIdx.x;
    const int r0 = blockIdx.x * 128;
    const int lane = tid & 31, w = tid >> 5;
    const int rA = (w & 3) * 32;
    const int nbase = (w >> 2) * 32;

    float acc[2][4][4];
    #pragma unroll
    for (int mi = 0; mi < 2; mi++)
        #pragma unroll
        for (int ni = 0; ni < 4; ni++)
            #pragma unroll
            for (int j = 0; j < 4; j++) acc[mi][ni][j] = 0.f;

    for (int ch = 0; ch < 2; ch++) {
        const int kc = ch * 32;
        __syncthreads();
        #pragma unroll
        for (int it = 0; it < 16; it++) {
            int idx = it * 256 + tid;
            int kk = idx & 31, r = idx >> 5;
            int gk = kc + kk;
            float v = (gk < HW) ? A[(size_t)(r0 + r) * HW + gk] : 0.f;
            split2(v, sA[0][r][kk], sA[1][r][kk]);
        }
        #pragma unroll
        for (int it = 0; it < 8; it++) {
            int idx = it * 256 + tid;
            int n = idx & 63, kk = idx >> 6;
            int gk = kc + kk;
            float v = (gk < HW && n < S2) ? d_P[gk * S2 + n] : 0.f;
            split2(v, sB[0][n][kk], sB[1][n][kk]);
        }
        __syncthreads();
        #pragma unroll
        for (int kk = 0; kk < 32; kk += 16) {
            uint32_t aH[2][4], aL[2][4];
            const int arow = rA + (lane & 7) + ((lane >> 3) & 1) * 8;
            const int akc  = kk + (lane >> 4) * 8;
            #pragma unroll
            for (int mi = 0; mi < 2; mi++) {
                ldsm4(smem_u32(&sA[0][arow + mi * 16][akc]), aH[mi]);
                ldsm4(smem_u32(&sA[1][arow + mi * 16][akc]), aL[mi]);
            }
            #pragma unroll
            for (int np = 0; np < 2; np++) {
                uint32_t bH[4], bL[4];
                const int brow = nbase + np * 16 + (lane >> 4) * 8 + (lane & 7);
                const int bkc  = kk + ((lane >> 3) & 1) * 8;
                ldsm4(smem_u32(&sB[0][brow][bkc]), bH);
                ldsm4(smem_u32(&sB[1][brow][bkc]), bL);
                #pragma unroll
                for (int mi = 0; mi < 2; mi++) {
                    #pragma unroll
                    for (int h = 0; h < 2; h++) {
                        int ni = 2 * np + h;
                        mma16816(acc[mi][ni], aH[mi], &bH[2 * h]);
                        mma16816(acc[mi][ni], aH[mi], &bL[2 * h]);
                        mma16816(acc[mi][ni], aL[mi], &bH[2 * h]);
                    }
                }
            }
        }
    }

    __syncthreads();
    bf16 (*sH)[128] = reinterpret_cast<bf16(*)[128]>(smr);          // [49][128]
    bf16 (*sL)[128] = reinterpret_cast<bf16(*)[128]>(smr + 12800);
    const int g2 = lane >> 2, tg = lane & 3;
    #pragma unroll
    for (int mi = 0; mi < 2; mi++) {
        #pragma unroll
        for (int ni = 0; ni < 4; ni++) {
            int rowl = rA + mi * 16 + g2;
            int col = nbase + ni * 8 + tg * 2;
            #pragma unroll
            for (int j = 0; j < 4; j++) {
                int rr = rowl + (j >> 1) * 8;
                int nn = col + (j & 1);
                if (nn < S2) {
                    bf16 h, l;
                    split2(acc[mi][ni][j], h, l);
                    sH[nn][rr] = h;
                    sL[nn][rr] = l;
                }
            }
        }
    }
    __syncthreads();
    for (int idx = tid; idx < S2 * 128; idx += 256) {
        int i = idx >> 7, r = idx & 127;
        size_t o = (size_t)i * BC + r0 + r;
        Ch[o] = sH[i][r];
        Cl[o] = sL[i][r];
    }
}

// ---------------------------------------------------------------------------
// Engine B (pre-split bf16 planes, cp.async double-buffered) — stageD/5/6.
// Runtime npMax (uniform per CTA): only npMax*32 B-columns are loaded/computed.
// ---------------------------------------------------------------------------
template<bool RELU, bool PACKOUT, bool LSEL>
__global__ void __launch_bounds__(256) mmag_p(
    const bf16* __restrict__ Ah, const bf16* __restrict__ Al,
    const bf16* __restrict__ Bh, const bf16* __restrict__ Bl,
    float* __restrict__ C, bf16* __restrict__ Ch, bf16* __restrict__ Cl,
    int lda, int ldb, int ldc, int Nreal, int npMaxIn,
    int kchunks, int kstride, int zdiv,
    size_t astride, size_t bstride, size_t cstride, size_t cstride2)
{
    extern __shared__ bf16 S[];   // sA[2buf][2pl][128][40] then sB same: 81920 B
    const int tid = threadIdx.x;
    const int z = blockIdx.z;
    const int batch = z >> zdiv;
    const int sub = z - (batch << zdiv);
    const bf16* Aph = Ah + (size_t)batch * astride;
    const bf16* Apl = Al + (size_t)batch * astride;
    const size_t boff = (LSEL ? (size_t)c_l_of_i[batch] : (size_t)batch) * bstride;
    const bf16* Bph = Bh + boff;
    const bf16* Bpl = Bl + boff;
    float* Cp = C + (size_t)batch * cstride + (size_t)sub * cstride2;
    const int kbeg = sub * kstride;
    const int r0 = blockIdx.y * 128;
    const int n0 = blockIdx.x * 128;
    const int lane = tid & 31, w = tid >> 5;
    const int rA = (w & 3) * 32;
    const int nbase = (w >> 2) * 64;
    const uint32_t sbase = smem_u32(S);
    constexpr uint32_t SBOFF = 2 * 2 * 128 * 40 * 2;   // bytes

    int npMax = npMaxIn;
    if (LSEL) {
        int d = 2 * c_l_of_i[batch] + 1;
        npMax = (8 * d + 31) >> 5;        // 1..4
    }

    float acc[2][8][4];
    #pragma unroll
    for (int mi = 0; mi < 2; mi++)
        #pragma unroll
        for (int ni = 0; ni < 8; ni++)
            #pragma unroll
            for (int j = 0; j < 4; j++) acc[mi][ni][j] = 0.f;

    auto copyin = [&](int buf, int kc) {
        #pragma unroll
        for (int it = 0; it < 8; it++) {
            int idx = it * 256 + tid;
            int q = idx & 7, r = (idx >> 3) & 127, p = idx >> 10;
            const bf16* g = (p ? Apl : Aph) + (size_t)(r0 + r) * lda + kc + q * 4;
            uint32_t d = sbase + (((buf * 2 + p) * 128 + r) * 40 + q * 4) * 2;
            asm volatile("cp.async.ca.shared.global [%0], [%1], 8;"
                         :: "r"(d), "l"(g));
        }
        // B: only npMax*32 rows per plane
        for (int p = 0; p < 2; p++) {
            for (int itn = 0; itn < npMax; itn++) {
                int q = tid & 7, r = itn * 32 + (tid >> 3);
                const bf16* g = (p ? Bpl : Bph) + (size_t)(n0 + r) * ldb + kc + q * 4;
                uint32_t d = sbase + SBOFF + (((buf * 2 + p) * 128 + r) * 40 + q * 4) * 2;
                asm volatile("cp.async.ca.shared.global [%0], [%1], 8;"
                             :: "r"(d), "l"(g));
            }
        }
        asm volatile("cp.async.commit_group;" ::: "memory");
    };

    int buf = 0;
    copyin(0, kbeg);

    for (int ch = 0; ch < kchunks; ch++) {
        if (ch + 1 < kchunks) {
            copyin(buf ^ 1, kbeg + (ch + 1) * 32);
            asm volatile("cp.async.wait_group 1;" ::: "memory");
        } else {
            asm volatile("cp.async.wait_group 0;" ::: "memory");
        }
        __syncthreads();

        #pragma unroll
        for (int kk = 0; kk < 32; kk += 16) {
            uint32_t aH[2][4], aL[2][4];
            const int arow = rA + (lane & 7) + ((lane >> 3) & 1) * 8;
            const int akc  = kk + (lane >> 4) * 8;
            #pragma unroll
            for (int mi = 0; mi < 2; mi++) {
                uint32_t a0 = sbase + (((buf * 2 + 0) * 128 + arow + mi * 16) * 40 + akc) * 2;
                uint32_t a1 = sbase + (((buf * 2 + 1) * 128 + arow + mi * 16) * 40 + akc) * 2;
                ldsm4(a0, aH[mi]);
                ldsm4(a1, aL[mi]);
            }
            #pragma unroll
            for (int np = 0; np < 4; np++) {
                // warp n-range: [nbase, nbase+64); global cols nbase+np*16
                if ((nbase >> 4) + np < (npMax << 1)) {
                    uint32_t bH[4], bL[4];
                    const int brow = nbase + np * 16 + (lane >> 4) * 8 + (lane & 7);
                    const int bkc  = kk + ((lane >> 3) & 1) * 8;
                    uint32_t b0 = sbase + SBOFF + (((buf * 2 + 0) * 128 + brow) * 40 + bkc) * 2;
                    uint32_t b1 = sbase + SBOFF + (((buf * 2 + 1) * 128 + brow) * 40 + bkc) * 2;
                    ldsm4(b0, bH);
                    ldsm4(b1, bL);
                    #pragma unroll
                    for (int mi = 0; mi < 2; mi++) {
                        #pragma unroll
                        for (int h = 0; h < 2; h++) {
                            int ni = 2 * np + h;
                            mma16816(acc[mi][ni], aH[mi], &bH[2 * h]);
                            mma16816(acc[mi][ni], aH[mi], &bL[2 * h]);
                            mma16816(acc[mi][ni], aL[mi], &bH[2 * h]);
                        }
                    }
                }
            }
        }
        __syncthreads();
        buf ^= 1;
    }

    const int g2 = lane >> 2, tg = lane & 3;
    #pragma unroll
    for (int mi = 0; mi < 2; mi++) {
        #pragma unroll
        for (int ni = 0; ni < 8; ni++) {
            if (((nbase + ni * 8) >> 5) >= npMax) continue;
            int row = r0 + rA + mi * 16 + g2;
            int col = n0 + nbase + ni * 8 + tg * 2;
            float v[4];
            #pragma unroll
            for (int j = 0; j < 4; j++) {
                v[j] = acc[mi][ni][j];
                if (RELU) v[j] = fmaxf(v[j], 0.f);
            }
            if (PACKOUT) {
                #pragma unroll
                for (int h = 0; h < 2; h++) {
                    int rr = row + h * 8;
                    bf16 h0, l0, h1, l1;
                    split2(v[2 * h + 0], h0, l0);
                    split2(v[2 * h + 1], h1, l1);
                    *(uint32_t*)&Ch[(size_t)rr * ldc + col] = pack2(h0, h1);
                    *(uint32_t*)&Cl[(size_t)rr * ldc + col] = pack2(l0, l1);
                }
            } else {
                #pragma unroll
                for (int j = 0; j < 4; j++) {
                    int rr = row + (j >> 1) * 8;
                    int nn = col + (j & 1);
                    if (nn < Nreal) Cp[(size_t)rr * ldc + nn] = v[j];
                }
            }
        }
    }
}

// ---------------------------------------------------------------------------
// Small kernels
// ---------------------------------------------------------------------------
__global__ void k_Pq(const float* __restrict__ proj_w, const float* __restrict__ proj_Y) {
    const int tid = threadIdx.x;
    for (int t = tid; t < HW * S2; t += 256) {
        int hw = t / S2, i = t % S2;
        const float* wr = proj_w + hw * NP;
        float acc = 0.f;
        #pragma unroll 8
        for (int n = 0; n < NP; n++) acc += wr[n] * proj_Y[n * S2 + i];
        d_P[t] = acc * RS192;
    }
    __syncthreads();
    if (tid < S2) {
        float a = 0.f;
        for (int hw = 0; hw < HW; hw++) a += d_P[hw * S2 + tid];
        d_q[tid] = a;
    }
}

__global__ void k_bpsi(const float* __restrict__ conv_b) {
    __shared__ float part[8][33];
    const int lane = threadIdx.x & 31, w = threadIdx.x >> 5;
    const int t = blockIdx.x * 32 + lane;
    float acc = 0.f;
    if (t < GI) {
        #pragma unroll 8
        for (int ff = 0; ff < 64; ff++) {
            int f = w * 64 + ff;
            acc += conv_b[f] * d_psi[f * GI + t];
        }
    }
    part[w][lane] = acc;
    __syncthreads();
    if (w == 0 && t < GI) {
        float s = 0.f;
        #pragma unroll
        for (int j = 0; j < 8; j++) s += part[j][lane];
        d_bpsi[t] = s * RS512;
    }
}

__global__ void k_psi2(const float* __restrict__ so3_w, const float* __restrict__ so3_D) {
    int w = (blockIdx.x * blockDim.x + threadIdx.x) >> 5;
    int lane = threadIdx.x & 31;
    if (w >= G_ * SO3) return;
    int f = w / SO3, i = w % SO3;
    float acc = 0.f;
    for (int n = lane; n < NP; n += 32) acc += so3_w[f * NP + n] * so3_D[n * SO3 + i];
    #pragma unroll
    for (int o = 16; o; o >>= 1) acc += __shfl_xor_sync(0xFFFFFFFFu, acc, o);
    if (lane == 0) d_psi2[w] = acc * RS192;
}

__global__ void k_tpose(const float* __restrict__ in, bf16* __restrict__ oh,
                        bf16* __restrict__ ol, int inR, int inC, int ldo) {
    __shared__ float tl[32][33];
    int n0 = blockIdx.x * 32, k0 = blockIdx.y * 32;
    #pragma unroll
    for (int j = 0; j < 4; j++) {
        int k = k0 + threadIdx.y + j * 8, n = n0 + threadIdx.x;
        tl[threadIdx.y + j * 8][threadIdx.x] =
            (k < inR && n < inC) ? in[(size_t)k * inC + n] : 0.f;
    }
    __syncthreads();
    #pragma unroll
    for (int j = 0; j < 4; j++) {
        int n = n0 + threadIdx.y + j * 8, k = k0 + threadIdx.x;
        bf16 h, l;
        split2(tl[threadIdx.x][threadIdx.y + j * 8], h, l);
        oh[(size_t)n * ldo + k] = h;
        ol[(size_t)n * ldo + k] = l;
    }
}

__global__ void k_w2t() {
    int t = blockIdx.x * blockDim.x + threadIdx.x;
    if (t >= 7 * 128 * C_) return;
    int l = t / (128 * C_);
    int r = t - l * 128 * C_;
    int j = r / C_, c = r - j * C_;
    int d = 2 * l + 1;
    float v = 0.f;
    if (j < 8 * d) {
        int g = j / d, u = j - g * d;
        v = d_W2c[(size_t)c * 448 + g * S2 + l * l + u];
    }
    bf16 h, lo;
    split2(v, h, lo);
    d_W2th[t] = h;
    d_W2tl[t] = lo;
}

// partD (8 k-slabs) + bias -> x4 planes [1024][512]
__global__ void k_x4() {
    int t = blockIdx.x * blockDim.x + threadIdx.x;
    if (t >= 1024 * 512) return;
    int row = t >> 9, col = t & 511;
    int b = row >> 3, g = row & 7;
    float v = 0.f;
    if (col < SO3) {
        int l = 6;
        while (col < c_off2[l]) l--;
        int d = 2 * l + 1, r = col - c_off2[l];
        int u = r / d, m = r - u * d, i = l * l + m;
        size_t o = (size_t)i * 128 * 104 + (size_t)b * 104 + g * d + u;
        float s = 0.f;
        #pragma unroll
        for (int zz = 0; zz < 8; zz++)
            s += d_partD[o + (size_t)zz * 49 * 128 * 104];
        v = s + d_bpsi[g * S2 + l * l + u] * d_q[l * l + m];
    }
    bf16 h, lo;
    split2(v, h, lo);
    d_x4h[t] = h;
    d_x4l[t] = lo;
}

__global__ void k_red6() {
    int t = blockIdx.x * blockDim.x + threadIdx.x;
    if (t >= 1024 * SO3) return;
    int row = t / SO3, col = t - row * SO3;
    float s = 0.f;
    #pragma unroll
    for (int zz = 0; zz < 8; zz++)
        s += d_part6[(size_t)zz * 1024 * 512 + (size_t)row * 512 + col];
    d_x5[t] = s;
}

__global__ void stageH_kernel(float* __restrict__ out) {
    int t = blockIdx.x * blockDim.x + threadIdx.x;
    if (t >= B_ * SO3) return;
    int b = t / SO3, j = t - b * SO3;
    int l = 6;
    while (j < c_off2[l]) l--;
    int d = 2 * l + 1;
    int r = j - c_off2[l];
    int v = r / d, m = r - v * d;
    float acc = 0.f;
    #pragma unroll
    for (int f = 0; f < G_; f++) {
        const float* xr = d_x5 + (size_t)(b * G_ + f) * SO3 + c_off2[l];
        const float* pr = d_psi2 + f * SO3 + c_off2[l];
        for (int u = 0; u < d; u++) acc += xr[u * d + m] * pr[u * d + v];
    }
    out[t] = acc * (1.0f / sqrtf(8.0f * d));
}

// ---------------------------------------------------------------------------
// Host launcher
// ---------------------------------------------------------------------------
extern "C" void kernel_launch(void* const* d_in, const int* in_sizes, int n_in,
                              void* d_out, int out_size) {
    const float* fmap     = (const float*)d_in[0];
    const float* conv_w   = (const float*)d_in[1];
    const float* conv_b   = (const float*)d_in[2];
    const float* proj_w   = (const float*)d_in[3];
    const float* proj_Y   = (const float*)d_in[4];
    const float* fs_w     = (const float*)d_in[5];
    const float* fs_Y     = (const float*)d_in[6];
    const float* act_to   = (const float*)d_in[7];
    const float* act_from = (const float*)d_in[8];
    const float* so3_w    = (const float*)d_in[9];
    const float* so3_D    = (const float*)d_in[10];
    float* out = (float*)d_out;

    float *pPsi, *pW2c, *pPartD, *pPart6;
    bf16 *pADh, *pADl, *pW2th, *pW2tl, *pX4h, *pX4l, *pB5h, *pB5l;
    bf16 *pGh, *pGl, *pB6h, *pB6l;
    cudaGetSymbolAddress((void**)&pPsi,   d_psi);
    cudaGetSymbolAddress((void**)&pW2c,   d_W2c);
    cudaGetSymbolAddress((void**)&pPartD, d_partD);
    cudaGetSymbolAddress((void**)&pPart6, d_part6);
    cudaGetSymbolAddress((void**)&pADh,   d_ADh);
    cudaGetSymbolAddress((void**)&pADl,   d_ADl);
    cudaGetSymbolAddress((void**)&pW2th,  d_W2th);
    cudaGetSymbolAddress((void**)&pW2tl,  d_W2tl);
    cudaGetSymbolAddress((void**)&pX4h,   d_x4h);
    cudaGetSymbolAddress((void**)&pX4l,   d_x4l);
    cudaGetSymbolAddress((void**)&pB5h,   d_bt5h);
    cudaGetSymbolAddress((void**)&pB5l,   d_bt5l);
    cudaGetSymbolAddress((void**)&pGh,    d_gacth);
    cudaGetSymbolAddress((void**)&pGl,    d_gactl);
    cudaGetSymbolAddress((void**)&pB6h,   d_bt6h);
    cudaGetSymbolAddress((void**)&pB6l,   d_bt6l);

    auto* kW2  = mmag_f<true,  true,  64>;
    auto* kPsi = mmag_f<false, true,  64>;
    auto* kSD = mmag_p<false, false, true >;
    auto* kS5 = mmag_p<true,  true,  false>;
    auto* kS6 = mmag_p<false, false, false>;
    constexpr int SMP = 2 * 2 * 2 * 128 * 40 * 2;   // 81920 B
    cudaFuncSetAttribute(kSD, cudaFuncAttributeMaxDynamicSharedMemorySize, SMP);
    cudaFuncSetAttribute(kS5, cudaFuncAttributeMaxDynamicSharedMemorySize, SMP);
    cudaFuncSetAttribute(kS6, cudaFuncAttributeMaxDynamicSharedMemorySize, SMP);

    // ---- critical-path front (order also places kSD at launch #5 for ncu) ----
    k_Pq<<<1, 256>>>(proj_w, proj_Y);
    // psi = RS192 * fs_w @ fs_Y   (M=4096, N=49, K=192)
    kPsi<<<dim3(1, 32, 1), 256>>>(fs_w, fs_Y, pPsi, NP, S2, S2, NP, S2, RS192, 6);
    // W2c = RS512 * conv_w^T @ psi   (M=2048, N=392, K=512)
    kW2<<<dim3(7, 16, 1), 256>>>(conv_w, pPsi, pW2c, C_, GI, 448, FIN, GI, RS512, 16);
    k_w2t<<<(7 * 128 * C_ + 255) / 256, 256>>>();
    // AD planes: (fmap @ P)^T  (M=262144, N=49, K=49)
    kAD_kernel<<<2048, 256>>>(fmap, pADh, pADl);

    // stageD: 49 batches (M=128, N=8d, K=2048), split-K x8, dynamic npMax
    kSD<<<dim3(1, 1, 392), 256, SMP>>>(pADh, pADl, pW2th, pW2tl,
        pPartD, (bf16*)0, (bf16*)0,
        C_, C_, 104, 104, 4, 8, 256, 3,
        BC, (size_t)128 * C_, (size_t)128 * 104, (size_t)49 * 128 * 104);

    // remaining small precomputes (off critical profile slot)
    k_bpsi<<<(GI + 31) / 32, 256>>>(conv_b);
    k_psi2<<<(G_ * SO3 * 32 + 127) / 128, 128>>>(so3_w, so3_D);
    k_x4<<<(1024 * 512 + 255) / 256, 256>>>();

    k_tpose<<<dim3(128, 15), dim3(32, 8)>>>(act_to,   pB5h, pB5l, SO3, NG, 480);
    // stage5: gact planes = relu(x4 @ act_to)  (M=1024, N=4096, K=480)
    kS5<<<dim3(32, 8, 1), 256, SMP>>>(pX4h, pX4l, pB5h, pB5l,
        (float*)0, pGh, pGl,
        512, 480, 4096, 4096, 4, 15, 0, 0, 0, 0, 0, 0);

    k_tpose<<<dim3(16, 128), dim3(32, 8)>>>(act_from, pB6h, pB6l, NG, SO3, 4096);
    // stage6: part6[z] = gact @ act_from  (M=1024, N=512, K=4096), split-K x8
    kS6<<<dim3(4, 8, 8), 256, SMP>>>(pGh, pGl, pB6h, pB6l,
        pPart6, (bf16*)0, (bf16*)0,
        4096, 4096, 512, 512, 4, 16, 512, 3,
        0, 0, 0, (size_t)1024 * 512);
    k_red6<<<(1024 * SO3 + 255) / 256, 256>>>();

    stageH_kernel<<<(B_ * SO3 + 255) / 256, 256>>>(out);
}

// round 13
// speedup vs baseline: 4.9325x; 1.2431x over previous
#include <cuda_runtime.h>
#include <cuda_bf16.h>
#include <math.h>
#include <stdint.h>

typedef __nv_bfloat16 bf16;

// ---------------------------------------------------------------------------
// Problem constants
// ---------------------------------------------------------------------------
static constexpr int B_   = 128;
static constexpr int C_   = 2048;
static constexpr int HW   = 49;
static constexpr int FIN  = 512;
static constexpr int G_   = 8;
static constexpr int NP   = 192;
static constexpr int S2   = 49;
static constexpr int SO3  = 455;
static constexpr int NG   = 4000;
static constexpr int GI   = 392;                // G_*S2
static constexpr size_t BC = (size_t)B_ * C_;   // 262144

static constexpr float RS192 = 0.07216878364870323f;
static constexpr float RS512 = 0.04419417382415922f;

// ---------------------------------------------------------------------------
// Scratch (device globals; runtime allocation is forbidden)
// ---------------------------------------------------------------------------
__device__ float d_P[HW * S2];
__device__ float d_q[S2];
__device__ float d_psi[FIN * GI];
__device__ float d_bpsi[GI];
__device__ float d_psi2[G_ * SO3];

// hi/lo bf16 planes (pre-split operands for the pipelined GEMMs)
__device__ __align__(16) bf16 d_ADh[(size_t)49 * BC];   // [i][b*2048+c]
__device__ __align__(16) bf16 d_ADl[(size_t)49 * BC];
// W2t planes: pad rows (j >= 8d) are NEVER written -> stay zero-initialized.
__device__ __align__(16) bf16 d_W2th[7 * 128 * C_];     // [l][j pad128][c]
__device__ __align__(16) bf16 d_W2tl[7 * 128 * C_];
__device__ __align__(16) bf16 d_x4h[1024 * 512];        // [b*8+g][so3 pad512]
__device__ __align__(16) bf16 d_x4l[1024 * 512];
__device__ __align__(16) bf16 d_bt5h[(size_t)4096 * 480]; // act_to^T planes
__device__ __align__(16) bf16 d_bt5l[(size_t)4096 * 480];
__device__ __align__(16) bf16 d_gacth[(size_t)1024 * 4096];
__device__ __align__(16) bf16 d_gactl[(size_t)1024 * 4096];
__device__ __align__(16) bf16 d_bt6h[(size_t)512 * 4096]; // act_from^T planes
__device__ __align__(16) bf16 d_bt6l[(size_t)512 * 4096];

__device__ float d_partD[(size_t)8 * 49 * 128 * 104];
__device__ float d_part6[(size_t)8 * 1024 * 512];
__device__ float d_x5[1024 * SO3];

__constant__ int c_off2[8] = {0, 1, 10, 35, 84, 165, 286, 455};
__constant__ int c_l_of_i[49] = {
    0, 1,1,1, 2,2,2,2,2, 3,3,3,3,3,3,3, 4,4,4,4,4,4,4,4,4,
    5,5,5,5,5,5,5,5,5,5,5, 6,6,6,6,6,6,6,6,6,6,6,6,6};

// ---------------------------------------------------------------------------
// helpers
// ---------------------------------------------------------------------------
__device__ __forceinline__ uint32_t smem_u32(const void* p) {
    uint32_t a;
    asm("{ .reg .u64 t; cvta.to.shared.u64 t, %1; cvt.u32.u64 %0, t; }"
        : "=r"(a) : "l"(p));
    return a;
}

__device__ __forceinline__ void ldsm4(uint32_t addr, uint32_t r[4]) {
    asm volatile("ldmatrix.sync.aligned.m8n8.x4.shared.b16 {%0,%1,%2,%3}, [%4];"
                 : "=r"(r[0]), "=r"(r[1]), "=r"(r[2]), "=r"(r[3]) : "r"(addr));
}

__device__ __forceinline__ void mma16816(float c[4], const uint32_t a[4],
                                         const uint32_t b[2]) {
    asm volatile(
        "mma.sync.aligned.m16n8k16.row.col.f32.bf16.bf16.f32 "
        "{%0,%1,%2,%3}, {%4,%5,%6,%7}, {%8,%9}, {%0,%1,%2,%3};"
        : "+f"(c[0]), "+f"(c[1]), "+f"(c[2]), "+f"(c[3])
        : "r"(a[0]), "r"(a[1]), "r"(a[2]), "r"(a[3]), "r"(b[0]), "r"(b[1]));
}

__device__ __forceinline__ void split2(float v, bf16& h, bf16& l) {
    h = __float2bfloat16(v);
    l = __float2bfloat16(v - __bfloat162float(h));
}

__device__ __forceinline__ uint32_t pack2(bf16 a, bf16 b) {
    return (uint32_t)__bfloat16_as_ushort(a) |
           ((uint32_t)__bfloat16_as_ushort(b) << 16);
}

// ---------------------------------------------------------------------------
// Engine A (fp32 inputs, split-on-load).
// EPI=0: plain fp32 store to C. EPI=1: permuted hi/lo store into W2t planes
// (row m = channel c, col n = gi -> (l, j=g*d+u); pad rows stay zero-init).
// ---------------------------------------------------------------------------
template<bool ATRANS, bool BTRANS, int NT, int EPI>
__global__ void __launch_bounds__(256) mmag_f(
    const float* __restrict__ A, const float* __restrict__ Bsrc,
    float* __restrict__ C,
    int lda, int ldb, int ldc, int Kreal, int Nreal, float alpha, int kchunks)
{
    constexpr int NT16 = NT / 16;
    __shared__ bf16 sA[2][128][40];
    __shared__ bf16 sB[2][NT][40];

    const int tid = threadIdx.x;
    const int r0 = blockIdx.y * 128;
    const int n0 = blockIdx.x * NT;
    const int lane = tid & 31, w = tid >> 5;
    const int wm = w & 3, wn = w >> 2;
    const int rA = wm * 32;
    const int nbase = wn * (NT / 2);

    float acc[2][NT16][4];
    #pragma unroll
    for (int mi = 0; mi < 2; mi++)
        #pragma unroll
        for (int ni = 0; ni < NT16; ni++)
            #pragma unroll
            for (int j = 0; j < 4; j++) acc[mi][ni][j] = 0.f;

    for (int ch = 0; ch < kchunks; ch++) {
        const int kc = ch * 32;
        __syncthreads();
        #pragma unroll
        for (int it = 0; it < 16; it++) {
            int idx = it * 256 + tid;
            int r, kk;
            if (ATRANS) { r = idx & 127; kk = idx >> 7; }
            else        { kk = idx & 31; r = idx >> 5;  }
            int gk = kc + kk;
            float v = 0.f;
            if (gk < Kreal)
                v = ATRANS ? A[(size_t)gk * lda + (r0 + r)]
                           : A[(size_t)(r0 + r) * lda + gk];
            split2(v, sA[0][r][kk], sA[1][r][kk]);
        }
        #pragma unroll
        for (int it = 0; it < NT / 8; it++) {
            int idx = it * 256 + tid;
            int n, kk;
            if (BTRANS) { n = idx & (NT - 1); kk = idx >> (NT == 128 ? 7 : 6); }
            else        { kk = idx & 31;      n = idx >> 5; }
            int gk = kc + kk, gn = n0 + n;
            float v = 0.f;
            if (gk < Kreal && gn < Nreal)
                v = BTRANS ? Bsrc[(size_t)gk * ldb + gn]
                           : Bsrc[(size_t)gn * ldb + gk];
            split2(v, sB[0][n][kk], sB[1][n][kk]);
        }
        __syncthreads();
        #pragma unroll
        for (int kk = 0; kk < 32; kk += 16) {
            uint32_t aH[2][4], aL[2][4];
            const int arow = rA + (lane & 7) + ((lane >> 3) & 1) * 8;
            const int akc  = kk + (lane >> 4) * 8;
            #pragma unroll
            for (int mi = 0; mi < 2; mi++) {
                ldsm4(smem_u32(&sA[0][arow + mi * 16][akc]), aH[mi]);
                ldsm4(smem_u32(&sA[1][arow + mi * 16][akc]), aL[mi]);
            }
            #pragma unroll
            for (int np = 0; np < NT16 / 2; np++) {
                uint32_t bH[4], bL[4];
                const int brow = nbase + np * 16 + (lane >> 4) * 8 + (lane & 7);
                const int bkc  = kk + ((lane >> 3) & 1) * 8;
                ldsm4(smem_u32(&sB[0][brow][bkc]), bH);
                ldsm4(smem_u32(&sB[1][brow][bkc]), bL);
                #pragma unroll
                for (int mi = 0; mi < 2; mi++) {
                    #pragma unroll
                    for (int h = 0; h < 2; h++) {
                        int ni = 2 * np + h;
                        mma16816(acc[mi][ni], aH[mi], &bH[2 * h]);
                        mma16816(acc[mi][ni], aH[mi], &bL[2 * h]);
                        mma16816(acc[mi][ni], aL[mi], &bH[2 * h]);
                    }
                }
            }
        }
    }

    const int g2 = lane >> 2, tg = lane & 3;
    #pragma unroll
    for (int mi = 0; mi < 2; mi++) {
        #pragma unroll
        for (int ni = 0; ni < NT16; ni++) {
            int row = r0 + rA + mi * 16 + g2;
            int col = n0 + nbase + ni * 8 + tg * 2;
            #pragma unroll
            for (int j = 0; j < 4; j++) {
                int rr = row + (j >> 1) * 8;
                int nn = col + (j & 1);
                if (nn < Nreal) {
                    float v = alpha * acc[mi][ni][j];
                    if (EPI == 0) {
                        C[(size_t)rr * ldc + nn] = v;
                    } else {
                        int g = nn / S2, i = nn - g * S2;
                        int l = c_l_of_i[i];
                        int u = i - l * l;
                        int jj = g * (2 * l + 1) + u;
                        size_t o = ((size_t)l * 128 + jj) * C_ + rr;
                        bf16 h, lo;
                        split2(v, h, lo);
                        d_W2th[o] = h;
                        d_W2tl[o] = lo;
                    }
                }
            }
        }
    }
}

// ---------------------------------------------------------------------------
// Specialized AD kernel: AD[i][bc] = sum_hw fmap[bc][hw] * P[hw][i]
// SMEM-staged coalesced transposed plane stores. grid.x = 2048.
// ---------------------------------------------------------------------------
__global__ void __launch_bounds__(256) kAD_kernel(
    const float* __restrict__ A, bf16* __restrict__ Ch, bf16* __restrict__ Cl)
{
    __shared__ __align__(16) char smr[30720];
    bf16 (*sA)[128][40] = reinterpret_cast<bf16(*)[128][40]>(smr);
    bf16 (*sB)[64][40]  = reinterpret_cast<bf16(*)[64][40]>(smr + 20480);

    const int tid = threadIdx.x;
    const int r0 = blockIdx.x * 128;
    const int lane = tid & 31, w = tid >> 5;
    const int rA = (w & 3) * 32;
    const int nbase = (w >> 2) * 32;

    float acc[2][4][4];
    #pragma unroll
    for (int mi = 0; mi < 2; mi++)
        #pragma unroll
        for (int ni = 0; ni < 4; ni++)
            #pragma unroll
            for (int j = 0; j < 4; j++) acc[mi][ni][j] = 0.f;

    for (int ch = 0; ch < 2; ch++) {
        const int kc = ch * 32;
        __syncthreads();
        #pragma unroll
        for (int it = 0; it < 16; it++) {
            int idx = it * 256 + tid;
            int kk = idx & 31, r = idx >> 5;
            int gk = kc + kk;
            float v = (gk < HW) ? A[(size_t)(r0 + r) * HW + gk] : 0.f;
            split2(v, sA[0][r][kk], sA[1][r][kk]);
        }
        #pragma unroll
        for (int it = 0; it < 8; it++) {
            int idx = it * 256 + tid;
            int n = idx & 63, kk = idx >> 6;
            int gk = kc + kk;
            float v = (gk < HW && n < S2) ? d_P[gk * S2 + n] : 0.f;
            split2(v, sB[0][n][kk], sB[1][n][kk]);
        }
        __syncthreads();
        #pragma unroll
        for (int kk = 0; kk < 32; kk += 16) {
            uint32_t aH[2][4], aL[2][4];
            const int arow = rA + (lane & 7) + ((lane >> 3) & 1) * 8;
            const int akc  = kk + (lane >> 4) * 8;
            #pragma unroll
            for (int mi = 0; mi < 2; mi++) {
                ldsm4(smem_u32(&sA[0][arow + mi * 16][akc]), aH[mi]);
                ldsm4(smem_u32(&sA[1][arow + mi * 16][akc]), aL[mi]);
            }
            #pragma unroll
            for (int np = 0; np < 2; np++) {
                uint32_t bH[4], bL[4];
                const int brow = nbase + np * 16 + (lane >> 4) * 8 + (lane & 7);
                const int bkc  = kk + ((lane >> 3) & 1) * 8;
                ldsm4(smem_u32(&sB[0][brow][bkc]), bH);
                ldsm4(smem_u32(&sB[1][brow][bkc]), bL);
                #pragma unroll
                for (int mi = 0; mi < 2; mi++) {
                    #pragma unroll
                    for (int h = 0; h < 2; h++) {
                        int ni = 2 * np + h;
                        mma16816(acc[mi][ni], aH[mi], &bH[2 * h]);
                        mma16816(acc[mi][ni], aH[mi], &bL[2 * h]);
                        mma16816(acc[mi][ni], aL[mi], &bH[2 * h]);
                    }
                }
            }
        }
    }

    __syncthreads();
    bf16 (*sH)[128] = reinterpret_cast<bf16(*)[128]>(smr);          // [49][128]
    bf16 (*sL)[128] = reinterpret_cast<bf16(*)[128]>(smr + 12800);
    const int g2 = lane >> 2, tg = lane & 3;
    #pragma unroll
    for (int mi = 0; mi < 2; mi++) {
        #pragma unroll
        for (int ni = 0; ni < 4; ni++) {
            int rowl = rA + mi * 16 + g2;
            int col = nbase + ni * 8 + tg * 2;
            #pragma unroll
            for (int j = 0; j < 4; j++) {
                int rr = rowl + (j >> 1) * 8;
                int nn = col + (j & 1);
                if (nn < S2) {
                    bf16 h, l;
                    split2(acc[mi][ni][j], h, l);
                    sH[nn][rr] = h;
                    sL[nn][rr] = l;
                }
            }
        }
    }
    __syncthreads();
    for (int idx = tid; idx < S2 * 128; idx += 256) {
        int i = idx >> 7, r = idx & 127;
        size_t o = (size_t)i * BC + r0 + r;
        Ch[o] = sH[i][r];
        Cl[o] = sL[i][r];
    }
}

// ---------------------------------------------------------------------------
// Engine B (pre-split bf16 planes, cp.async double-buffered) — stageD/5/6.
// Runtime npMax (uniform per CTA): only npMax*32 B-columns loaded/computed.
// ---------------------------------------------------------------------------
template<bool RELU, bool PACKOUT, bool LSEL>
__global__ void __launch_bounds__(256) mmag_p(
    const bf16* __restrict__ Ah, const bf16* __restrict__ Al,
    const bf16* __restrict__ Bh, const bf16* __restrict__ Bl,
    float* __restrict__ C, bf16* __restrict__ Ch, bf16* __restrict__ Cl,
    int lda, int ldb, int ldc, int Nreal, int npMaxIn,
    int kchunks, int kstride, int zdiv,
    size_t astride, size_t bstride, size_t cstride, size_t cstride2)
{
    extern __shared__ bf16 S[];   // sA[2buf][2pl][128][40] then sB same: 81920 B
    const int tid = threadIdx.x;
    const int z = blockIdx.z;
    const int batch = z >> zdiv;
    const int sub = z - (batch << zdiv);
    const bf16* Aph = Ah + (size_t)batch * astride;
    const bf16* Apl = Al + (size_t)batch * astride;
    const size_t boff = (LSEL ? (size_t)c_l_of_i[batch] : (size_t)batch) * bstride;
    const bf16* Bph = Bh + boff;
    const bf16* Bpl = Bl + boff;
    float* Cp = C + (size_t)batch * cstride + (size_t)sub * cstride2;
    const int kbeg = sub * kstride;
    const int r0 = blockIdx.y * 128;
    const int n0 = blockIdx.x * 128;
    const int lane = tid & 31, w = tid >> 5;
    const int rA = (w & 3) * 32;
    const int nbase = (w >> 2) * 64;
    const uint32_t sbase = smem_u32(S);
    constexpr uint32_t SBOFF = 2 * 2 * 128 * 40 * 2;   // bytes

    int npMax = npMaxIn;
    if (LSEL) {
        int d = 2 * c_l_of_i[batch] + 1;
        npMax = (8 * d + 31) >> 5;        // 1..4
    }

    float acc[2][8][4];
    #pragma unroll
    for (int mi = 0; mi < 2; mi++)
        #pragma unroll
        for (int ni = 0; ni < 8; ni++)
            #pragma unroll
            for (int j = 0; j < 4; j++) acc[mi][ni][j] = 0.f;

    auto copyin = [&](int buf, int kc) {
        #pragma unroll
        for (int it = 0; it < 8; it++) {
            int idx = it * 256 + tid;
            int q = idx & 7, r = (idx >> 3) & 127, p = idx >> 10;
            const bf16* g = (p ? Apl : Aph) + (size_t)(r0 + r) * lda + kc + q * 4;
            uint32_t d = sbase + (((buf * 2 + p) * 128 + r) * 40 + q * 4) * 2;
            asm volatile("cp.async.ca.shared.global [%0], [%1], 8;"
                         :: "r"(d), "l"(g));
        }
        for (int p = 0; p < 2; p++) {
            for (int itn = 0; itn < npMax; itn++) {
                int q = tid & 7, r = itn * 32 + (tid >> 3);
                const bf16* g = (p ? Bpl : Bph) + (size_t)(n0 + r) * ldb + kc + q * 4;
                uint32_t d = sbase + SBOFF + (((buf * 2 + p) * 128 + r) * 40 + q * 4) * 2;
                asm volatile("cp.async.ca.shared.global [%0], [%1], 8;"
                             :: "r"(d), "l"(g));
            }
        }
        asm volatile("cp.async.commit_group;" ::: "memory");
    };

    int buf = 0;
    copyin(0, kbeg);

    for (int ch = 0; ch < kchunks; ch++) {
        if (ch + 1 < kchunks) {
            copyin(buf ^ 1, kbeg + (ch + 1) * 32);
            asm volatile("cp.async.wait_group 1;" ::: "memory");
        } else {
            asm volatile("cp.async.wait_group 0;" ::: "memory");
        }
        __syncthreads();

        #pragma unroll
        for (int kk = 0; kk < 32; kk += 16) {
            uint32_t aH[2][4], aL[2][4];
            const int arow = rA + (lane & 7) + ((lane >> 3) & 1) * 8;
            const int akc  = kk + (lane >> 4) * 8;
            #pragma unroll
            for (int mi = 0; mi < 2; mi++) {
                uint32_t a0 = sbase + (((buf * 2 + 0) * 128 + arow + mi * 16) * 40 + akc) * 2;
                uint32_t a1 = sbase + (((buf * 2 + 1) * 128 + arow + mi * 16) * 40 + akc) * 2;
                ldsm4(a0, aH[mi]);
                ldsm4(a1, aL[mi]);
            }
            #pragma unroll
            for (int np = 0; np < 4; np++) {
                if ((nbase >> 4) + np < (npMax << 1)) {
                    uint32_t bH[4], bL[4];
                    const int brow = nbase + np * 16 + (lane >> 4) * 8 + (lane & 7);
                    const int bkc  = kk + ((lane >> 3) & 1) * 8;
                    uint32_t b0 = sbase + SBOFF + (((buf * 2 + 0) * 128 + brow) * 40 + bkc) * 2;
                    uint32_t b1 = sbase + SBOFF + (((buf * 2 + 1) * 128 + brow) * 40 + bkc) * 2;
                    ldsm4(b0, bH);
                    ldsm4(b1, bL);
                    #pragma unroll
                    for (int mi = 0; mi < 2; mi++) {
                        #pragma unroll
                        for (int h = 0; h < 2; h++) {
                            int ni = 2 * np + h;
                            mma16816(acc[mi][ni], aH[mi], &bH[2 * h]);
                            mma16816(acc[mi][ni], aH[mi], &bL[2 * h]);
                            mma16816(acc[mi][ni], aL[mi], &bH[2 * h]);
                        }
                    }
                }
            }
        }
        __syncthreads();
        buf ^= 1;
    }

    const int g2 = lane >> 2, tg = lane & 3;
    #pragma unroll
    for (int mi = 0; mi < 2; mi++) {
        #pragma unroll
        for (int ni = 0; ni < 8; ni++) {
            if (((nbase + ni * 8) >> 5) >= npMax) continue;
            int row = r0 + rA + mi * 16 + g2;
            int col = n0 + nbase + ni * 8 + tg * 2;
            float v[4];
            #pragma unroll
            for (int j = 0; j < 4; j++) {
                v[j] = acc[mi][ni][j];
                if (RELU) v[j] = fmaxf(v[j], 0.f);
            }
            if (PACKOUT) {
                #pragma unroll
                for (int h = 0; h < 2; h++) {
                    int rr = row + h * 8;
                    bf16 h0, l0, h1, l1;
                    split2(v[2 * h + 0], h0, l0);
                    split2(v[2 * h + 1], h1, l1);
                    *(uint32_t*)&Ch[(size_t)rr * ldc + col] = pack2(h0, h1);
                    *(uint32_t*)&Cl[(size_t)rr * ldc + col] = pack2(l0, l1);
                }
            } else {
                #pragma unroll
                for (int j = 0; j < 4; j++) {
                    int rr = row + (j >> 1) * 8;
                    int nn = col + (j & 1);
                    if (nn < Nreal) Cp[(size_t)rr * ldc + nn] = v[j];
                }
            }
        }
    }
}

// ---------------------------------------------------------------------------
// Small kernels
// ---------------------------------------------------------------------------
__global__ void k_Pq(const float* __restrict__ proj_w, const float* __restrict__ proj_Y) {
    const int tid = threadIdx.x;
    for (int t = tid; t < HW * S2; t += 256) {
        int hw = t / S2, i = t % S2;
        const float* wr = proj_w + hw * NP;
        float acc = 0.f;
        #pragma unroll 8
        for (int n = 0; n < NP; n++) acc += wr[n] * proj_Y[n * S2 + i];
        d_P[t] = acc * RS192;
    }
    __syncthreads();
    if (tid < S2) {
        float a = 0.f;
        for (int hw = 0; hw < HW; hw++) a += d_P[hw * S2 + tid];
        d_q[tid] = a;
    }
}

__global__ void k_bpsi(const float* __restrict__ conv_b) {
    __shared__ float part[8][33];
    const int lane = threadIdx.x & 31, w = threadIdx.x >> 5;
    const int t = blockIdx.x * 32 + lane;
    float acc = 0.f;
    if (t < GI) {
        #pragma unroll 8
        for (int ff = 0; ff < 64; ff++) {
            int f = w * 64 + ff;
            acc += conv_b[f] * d_psi[f * GI + t];
        }
    }
    part[w][lane] = acc;
    __syncthreads();
    if (w == 0 && t < GI) {
        float s = 0.f;
        #pragma unroll
        for (int j = 0; j < 8; j++) s += part[j][lane];
        d_bpsi[t] = s * RS512;
    }
}

__global__ void k_psi2(const float* __restrict__ so3_w, const float* __restrict__ so3_D) {
    int w = (blockIdx.x * blockDim.x + threadIdx.x) >> 5;
    int lane = threadIdx.x & 31;
    if (w >= G_ * SO3) return;
    int f = w / SO3, i = w % SO3;
    float acc = 0.f;
    for (int n = lane; n < NP; n += 32) acc += so3_w[f * NP + n] * so3_D[n * SO3 + i];
    #pragma unroll
    for (int o = 16; o; o >>= 1) acc += __shfl_xor_sync(0xFFFFFFFFu, acc, o);
    if (lane == 0) d_psi2[w] = acc * RS192;
}

__global__ void k_tpose(const float* __restrict__ in, bf16* __restrict__ oh,
                        bf16* __restrict__ ol, int inR, int inC, int ldo) {
    __shared__ float tl[32][33];
    int n0 = blockIdx.x * 32, k0 = blockIdx.y * 32;
    #pragma unroll
    for (int j = 0; j < 4; j++) {
        int k = k0 + threadIdx.y + j * 8, n = n0 + threadIdx.x;
        tl[threadIdx.y + j * 8][threadIdx.x] =
            (k < inR && n < inC) ? in[(size_t)k * inC + n] : 0.f;
    }
    __syncthreads();
    #pragma unroll
    for (int j = 0; j < 4; j++) {
        int n = n0 + threadIdx.y + j * 8, k = k0 + threadIdx.x;
        bf16 h, l;
        split2(tl[threadIdx.x][threadIdx.y + j * 8], h, l);
        oh[(size_t)n * ldo + k] = h;
        ol[(size_t)n * ldo + k] = l;
    }
}

// partD (8 k-slabs) + bias -> x4 planes [1024][512]
__global__ void k_x4() {
    int t = blockIdx.x * blockDim.x + threadIdx.x;
    if (t >= 1024 * 512) return;
    int row = t >> 9, col = t & 511;
    int b = row >> 3, g = row & 7;
    float v = 0.f;
    if (col < SO3) {
        int l = 6;
        while (col < c_off2[l]) l--;
        int d = 2 * l + 1, r = col - c_off2[l];
        int u = r / d, m = r - u * d, i = l * l + m;
        size_t o = (size_t)i * 128 * 104 + (size_t)b * 104 + g * d + u;
        float s = 0.f;
        #pragma unroll
        for (int zz = 0; zz < 8; zz++)
            s += d_partD[o + (size_t)zz * 49 * 128 * 104];
        v = s + d_bpsi[g * S2 + l * l + u] * d_q[l * l + m];
    }
    bf16 h, lo;
    split2(v, h, lo);
    d_x4h[t] = h;
    d_x4l[t] = lo;
}

__global__ void k_red6() {
    int t = blockIdx.x * blockDim.x + threadIdx.x;
    if (t >= 1024 * SO3) return;
    int row = t / SO3, col = t - row * SO3;
    float s = 0.f;
    #pragma unroll
    for (int zz = 0; zz < 8; zz++)
        s += d_part6[(size_t)zz * 1024 * 512 + (size_t)row * 512 + col];
    d_x5[t] = s;
}

__global__ void stageH_kernel(float* __restrict__ out) {
    int t = blockIdx.x * blockDim.x + threadIdx.x;
    if (t >= B_ * SO3) return;
    int b = t / SO3, j = t - b * SO3;
    int l = 6;
    while (j < c_off2[l]) l--;
    int d = 2 * l + 1;
    int r = j - c_off2[l];
    int v = r / d, m = r - v * d;
    float acc = 0.f;
    #pragma unroll
    for (int f = 0; f < G_; f++) {
        const float* xr = d_x5 + (size_t)(b * G_ + f) * SO3 + c_off2[l];
        const float* pr = d_psi2 + f * SO3 + c_off2[l];
        for (int u = 0; u < d; u++) acc += xr[u * d + m] * pr[u * d + v];
    }
    out[t] = acc * (1.0f / sqrtf(8.0f * d));
}

// ---------------------------------------------------------------------------
// Host launcher — multi-stream fork/join (capture-legal via events)
// ---------------------------------------------------------------------------
extern "C" void kernel_launch(void* const* d_in, const int* in_sizes, int n_in,
                              void* d_out, int out_size) {
    const float* fmap     = (const float*)d_in[0];
    const float* conv_w   = (const float*)d_in[1];
    const float* conv_b   = (const float*)d_in[2];
    const float* proj_w   = (const float*)d_in[3];
    const float* proj_Y   = (const float*)d_in[4];
    const float* fs_w     = (const float*)d_in[5];
    const float* fs_Y     = (const float*)d_in[6];
    const float* act_to   = (const float*)d_in[7];
    const float* act_from = (const float*)d_in[8];
    const float* so3_w    = (const float*)d_in[9];
    const float* so3_D    = (const float*)d_in[10];
    float* out = (float*)d_out;

    float *pPsi, *pPartD, *pPart6;
    bf16 *pADh, *pADl, *pW2th, *pW2tl, *pX4h, *pX4l, *pB5h, *pB5l;
    bf16 *pGh, *pGl, *pB6h, *pB6l;
    cudaGetSymbolAddress((void**)&pPsi,   d_psi);
    cudaGetSymbolAddress((void**)&pPartD, d_partD);
    cudaGetSymbolAddress((void**)&pPart6, d_part6);
    cudaGetSymbolAddress((void**)&pADh,   d_ADh);
    cudaGetSymbolAddress((void**)&pADl,   d_ADl);
    cudaGetSymbolAddress((void**)&pW2th,  d_W2th);
    cudaGetSymbolAddress((void**)&pW2tl,  d_W2tl);
    cudaGetSymbolAddress((void**)&pX4h,   d_x4h);
    cudaGetSymbolAddress((void**)&pX4l,   d_x4l);
    cudaGetSymbolAddress((void**)&pB5h,   d_bt5h);
    cudaGetSymbolAddress((void**)&pB5l,   d_bt5l);
    cudaGetSymbolAddress((void**)&pGh,    d_gacth);
    cudaGetSymbolAddress((void**)&pGl,    d_gactl);
    cudaGetSymbolAddress((void**)&pB6h,   d_bt6h);
    cudaGetSymbolAddress((void**)&pB6l,   d_bt6l);

    auto* kPsi = mmag_f<false, true, 64, 0>;
    auto* kW2  = mmag_f<true,  true, 64, 1>;
    auto* kSD = mmag_p<false, false, true >;
    auto* kS5 = mmag_p<true,  true,  false>;
    auto* kS6 = mmag_p<false, false, false>;
    constexpr int SMP = 2 * 2 * 2 * 128 * 40 * 2;   // 81920 B
    cudaFuncSetAttribute(kSD, cudaFuncAttributeMaxDynamicSharedMemorySize, SMP);
    cudaFuncSetAttribute(kS5, cudaFuncAttributeMaxDynamicSharedMemorySize, SMP);
    cudaFuncSetAttribute(kS6, cudaFuncAttributeMaxDynamicSharedMemorySize, SMP);

    // one-time host-side infra (no device memory, identical GPU work per call)
    static cudaStream_t s1 = nullptr, s2 = nullptr;
    static cudaEvent_t evRoot = nullptr, evW2 = nullptr, evBps = nullptr, evAux = nullptr;
    if (s1 == nullptr) {
        cudaStreamCreateWithFlags(&s1, cudaStreamNonBlocking);
        cudaStreamCreateWithFlags(&s2, cudaStreamNonBlocking);
        cudaEventCreateWithFlags(&evRoot, cudaEventDisableTiming);
        cudaEventCreateWithFlags(&evW2,   cudaEventDisableTiming);
        cudaEventCreateWithFlags(&evBps,  cudaEventDisableTiming);
        cudaEventCreateWithFlags(&evAux,  cudaEventDisableTiming);
    }

    // fork: s1 (W2 chain), s2 (operand preps) join the capture via evRoot
    cudaEventRecord(evRoot, 0);
    cudaStreamWaitEvent(s1, evRoot, 0);
    cudaStreamWaitEvent(s2, evRoot, 0);

    // main chain
    k_Pq<<<1, 256>>>(proj_w, proj_Y);

    // s1: psi -> W2t (direct permuted store) -> bpsi
    kPsi<<<dim3(1, 32, 1), 256, 0, s1>>>(fs_w, fs_Y, pPsi,
                                         NP, S2, S2, NP, S2, RS192, 6);
    kW2<<<dim3(7, 16, 1), 256, 0, s1>>>(conv_w, pPsi, (float*)0,
                                        C_, GI, 0, FIN, GI, RS512, 16);
    cudaEventRecord(evW2, s1);
    k_bpsi<<<(GI + 31) / 32, 256, 0, s1>>>(conv_b);
    cudaEventRecord(evBps, s1);

    // s2: operand preps
    k_psi2<<<(G_ * SO3 * 32 + 127) / 128, 128, 0, s2>>>(so3_w, so3_D);
    k_tpose<<<dim3(128, 15), dim3(32, 8), 0, s2>>>(act_to,   pB5h, pB5l, SO3, NG, 480);
    k_tpose<<<dim3(16, 128), dim3(32, 8), 0, s2>>>(act_from, pB6h, pB6l, NG, SO3, 4096);
    cudaEventRecord(evAux, s2);

    // main chain continues
    kAD_kernel<<<2048, 256>>>(fmap, pADh, pADl);

    cudaStreamWaitEvent(0, evW2, 0);
    // stageD: 49 batches (M=128, N=8d, K=2048), split-K x8, dynamic npMax
    kSD<<<dim3(1, 1, 392), 256, SMP>>>(pADh, pADl, pW2th, pW2tl,
        pPartD, (bf16*)0, (bf16*)0,
        C_, C_, 104, 104, 4, 8, 256, 3,
        BC, (size_t)128 * C_, (size_t)128 * 104, (size_t)49 * 128 * 104);

    cudaStreamWaitEvent(0, evBps, 0);
    k_x4<<<(1024 * 512 + 255) / 256, 256>>>();

    cudaStreamWaitEvent(0, evAux, 0);
    // stage5: gact planes = relu(x4 @ act_to)  (M=1024, N=4096, K=480)
    kS5<<<dim3(32, 8, 1), 256, SMP>>>(pX4h, pX4l, pB5h, pB5l,
        (float*)0, pGh, pGl,
        512, 480, 4096, 4096, 4, 15, 0, 0, 0, 0, 0, 0);

    // stage6: part6[z] = gact @ act_from  (M=1024, N=512, K=4096), split-K x8
    kS6<<<dim3(4, 8, 8), 256, SMP>>>(pGh, pGl, pB6h, pB6l,
        pPart6, (bf16*)0, (bf16*)0,
        4096, 4096, 512, 512, 4, 16, 512, 3,
        0, 0, 0, (size_t)1024 * 512);
    k_red6<<<(1024 * SO3 + 255) / 256, 256>>>();

    stageH_kernel<<<(B_ * SO3 + 255) / 256, 256>>>(out);
}

// round 14
// speedup vs baseline: 4.9750x; 1.0086x over previous
#include <cuda_runtime.h>
#include <cuda_bf16.h>
#include <math.h>
#include <stdint.h>

typedef __nv_bfloat16 bf16;

// ---------------------------------------------------------------------------
// Problem constants
// ---------------------------------------------------------------------------
static constexpr int B_   = 128;
static constexpr int C_   = 2048;
static constexpr int HW   = 49;
static constexpr int FIN  = 512;
static constexpr int G_   = 8;
static constexpr int NP   = 192;
static constexpr int S2   = 49;
static constexpr int SO3  = 455;
static constexpr int NG   = 4000;
static constexpr int GI   = 392;                // G_*S2
static constexpr size_t BC = (size_t)B_ * C_;   // 262144

static constexpr float RS192 = 0.07216878364870323f;
static constexpr float RS512 = 0.04419417382415922f;

// ---------------------------------------------------------------------------
// Scratch (device globals; runtime allocation is forbidden)
// ---------------------------------------------------------------------------
__device__ float d_P[HW * S2];
__device__ float d_q[S2];
__device__ float d_psi[FIN * GI];
__device__ float d_bpsi[GI];
__device__ float d_psi2[G_ * SO3];

// hi/lo bf16 planes (pre-split operands for the pipelined GEMMs)
__device__ __align__(16) bf16 d_ADh[(size_t)49 * BC];   // [i][b*2048+c]
__device__ __align__(16) bf16 d_ADl[(size_t)49 * BC];
// W2t planes: pad rows (j >= 8d) are NEVER written -> stay zero-initialized.
__device__ __align__(16) bf16 d_W2th[7 * 128 * C_];     // [l][j pad128][c]
__device__ __align__(16) bf16 d_W2tl[7 * 128 * C_];
__device__ __align__(16) bf16 d_x4h[1024 * 512];        // [b*8+g][so3 pad512]
__device__ __align__(16) bf16 d_x4l[1024 * 512];
__device__ __align__(16) bf16 d_bt5h[(size_t)4096 * 480]; // act_to^T planes
__device__ __align__(16) bf16 d_bt5l[(size_t)4096 * 480];
__device__ __align__(16) bf16 d_gacth[(size_t)1024 * 4096];
__device__ __align__(16) bf16 d_gactl[(size_t)1024 * 4096];
__device__ __align__(16) bf16 d_bt6h[(size_t)512 * 4096]; // act_from^T planes
__device__ __align__(16) bf16 d_bt6l[(size_t)512 * 4096];

__device__ float d_partD[(size_t)6 * 49 * 128 * 104];
__device__ float d_part6[(size_t)8 * 1024 * 512];
__device__ float d_x5[1024 * SO3];

__constant__ int c_off2[8] = {0, 1, 10, 35, 84, 165, 286, 455};
__constant__ int c_l_of_i[49] = {
    0, 1,1,1, 2,2,2,2,2, 3,3,3,3,3,3,3, 4,4,4,4,4,4,4,4,4,
    5,5,5,5,5,5,5,5,5,5,5, 6,6,6,6,6,6,6,6,6,6,6,6,6};

// ---------------------------------------------------------------------------
// helpers
// ---------------------------------------------------------------------------
__device__ __forceinline__ uint32_t smem_u32(const void* p) {
    uint32_t a;
    asm("{ .reg .u64 t; cvta.to.shared.u64 t, %1; cvt.u32.u64 %0, t; }"
        : "=r"(a) : "l"(p));
    return a;
}

__device__ __forceinline__ void ldsm4(uint32_t addr, uint32_t r[4]) {
    asm volatile("ldmatrix.sync.aligned.m8n8.x4.shared.b16 {%0,%1,%2,%3}, [%4];"
                 : "=r"(r[0]), "=r"(r[1]), "=r"(r[2]), "=r"(r[3]) : "r"(addr));
}

__device__ __forceinline__ void mma16816(float c[4], const uint32_t a[4],
                                         const uint32_t b[2]) {
    asm volatile(
        "mma.sync.aligned.m16n8k16.row.col.f32.bf16.bf16.f32 "
        "{%0,%1,%2,%3}, {%4,%5,%6,%7}, {%8,%9}, {%0,%1,%2,%3};"
        : "+f"(c[0]), "+f"(c[1]), "+f"(c[2]), "+f"(c[3])
        : "r"(a[0]), "r"(a[1]), "r"(a[2]), "r"(a[3]), "r"(b[0]), "r"(b[1]));
}

__device__ __forceinline__ void split2(float v, bf16& h, bf16& l) {
    h = __float2bfloat16(v);
    l = __float2bfloat16(v - __bfloat162float(h));
}

__device__ __forceinline__ uint32_t pack2(bf16 a, bf16 b) {
    return (uint32_t)__bfloat16_as_ushort(a) |
           ((uint32_t)__bfloat16_as_ushort(b) << 16);
}

// ---------------------------------------------------------------------------
// Engine A (fp32 inputs, split-on-load).
// EPI=0: plain fp32 store to C. EPI=1: permuted hi/lo store into W2t planes.
// ---------------------------------------------------------------------------
template<bool ATRANS, bool BTRANS, int NT, int EPI>
__global__ void __launch_bounds__(256) mmag_f(
    const float* __restrict__ A, const float* __restrict__ Bsrc,
    float* __restrict__ C,
    int lda, int ldb, int ldc, int Kreal, int Nreal, float alpha, int kchunks)
{
    constexpr int NT16 = NT / 16;
    __shared__ bf16 sA[2][128][40];
    __shared__ bf16 sB[2][NT][40];

    const int tid = threadIdx.x;
    const int r0 = blockIdx.y * 128;
    const int n0 = blockIdx.x * NT;
    const int lane = tid & 31, w = tid >> 5;
    const int wm = w & 3, wn = w >> 2;
    const int rA = wm * 32;
    const int nbase = wn * (NT / 2);

    float acc[2][NT16][4];
    #pragma unroll
    for (int mi = 0; mi < 2; mi++)
        #pragma unroll
        for (int ni = 0; ni < NT16; ni++)
            #pragma unroll
            for (int j = 0; j < 4; j++) acc[mi][ni][j] = 0.f;

    for (int ch = 0; ch < kchunks; ch++) {
        const int kc = ch * 32;
        __syncthreads();
        #pragma unroll
        for (int it = 0; it < 16; it++) {
            int idx = it * 256 + tid;
            int r, kk;
            if (ATRANS) { r = idx & 127; kk = idx >> 7; }
            else        { kk = idx & 31; r = idx >> 5;  }
            int gk = kc + kk;
            float v = 0.f;
            if (gk < Kreal)
                v = ATRANS ? A[(size_t)gk * lda + (r0 + r)]
                           : A[(size_t)(r0 + r) * lda + gk];
            split2(v, sA[0][r][kk], sA[1][r][kk]);
        }
        #pragma unroll
        for (int it = 0; it < NT / 8; it++) {
            int idx = it * 256 + tid;
            int n, kk;
            if (BTRANS) { n = idx & (NT - 1); kk = idx >> (NT == 128 ? 7 : 6); }
            else        { kk = idx & 31;      n = idx >> 5; }
            int gk = kc + kk, gn = n0 + n;
            float v = 0.f;
            if (gk < Kreal && gn < Nreal)
                v = BTRANS ? Bsrc[(size_t)gk * ldb + gn]
                           : Bsrc[(size_t)gn * ldb + gk];
            split2(v, sB[0][n][kk], sB[1][n][kk]);
        }
        __syncthreads();
        #pragma unroll
        for (int kk = 0; kk < 32; kk += 16) {
            uint32_t aH[2][4], aL[2][4];
            const int arow = rA + (lane & 7) + ((lane >> 3) & 1) * 8;
            const int akc  = kk + (lane >> 4) * 8;
            #pragma unroll
            for (int mi = 0; mi < 2; mi++) {
                ldsm4(smem_u32(&sA[0][arow + mi * 16][akc]), aH[mi]);
                ldsm4(smem_u32(&sA[1][arow + mi * 16][akc]), aL[mi]);
            }
            #pragma unroll
            for (int np = 0; np < NT16 / 2; np++) {
                uint32_t bH[4], bL[4];
                const int brow = nbase + np * 16 + (lane >> 4) * 8 + (lane & 7);
                const int bkc  = kk + ((lane >> 3) & 1) * 8;
                ldsm4(smem_u32(&sB[0][brow][bkc]), bH);
                ldsm4(smem_u32(&sB[1][brow][bkc]), bL);
                #pragma unroll
                for (int mi = 0; mi < 2; mi++) {
                    #pragma unroll
                    for (int h = 0; h < 2; h++) {
                        int ni = 2 * np + h;
                        mma16816(acc[mi][ni], aH[mi], &bH[2 * h]);
                        mma16816(acc[mi][ni], aH[mi], &bL[2 * h]);
                        mma16816(acc[mi][ni], aL[mi], &bH[2 * h]);
                    }
                }
            }
        }
    }

    const int g2 = lane >> 2, tg = lane & 3;
    #pragma unroll
    for (int mi = 0; mi < 2; mi++) {
        #pragma unroll
        for (int ni = 0; ni < NT16; ni++) {
            int row = r0 + rA + mi * 16 + g2;
            int col = n0 + nbase + ni * 8 + tg * 2;
            #pragma unroll
            for (int j = 0; j < 4; j++) {
                int rr = row + (j >> 1) * 8;
                int nn = col + (j & 1);
                if (nn < Nreal) {
                    float v = alpha * acc[mi][ni][j];
                    if (EPI == 0) {
                        C[(size_t)rr * ldc + nn] = v;
                    } else {
                        int g = nn / S2, i = nn - g * S2;
                        int l = c_l_of_i[i];
                        int u = i - l * l;
                        int jj = g * (2 * l + 1) + u;
                        size_t o = ((size_t)l * 128 + jj) * C_ + rr;
                        bf16 h, lo;
                        split2(v, h, lo);
                        d_W2th[o] = h;
                        d_W2tl[o] = lo;
                    }
                }
            }
        }
    }
}

// ---------------------------------------------------------------------------
// Specialized AD kernel: AD[i][bc] = sum_hw fmap[bc][hw] * P[hw][i]
// SMEM-staged coalesced transposed plane stores. grid.x = 2048.
// ---------------------------------------------------------------------------
__global__ void __launch_bounds__(256) kAD_kernel(
    const float* __restrict__ A, bf16* __restrict__ Ch, bf16* __restrict__ Cl)
{
    __shared__ __align__(16) char smr[30720];
    bf16 (*sA)[128][40] = reinterpret_cast<bf16(*)[128][40]>(smr);
    bf16 (*sB)[64][40]  = reinterpret_cast<bf16(*)[64][40]>(smr + 20480);

    const int tid = threadIdx.x;
    const int r0 = blockIdx.x * 128;
    const int lane = tid & 31, w = tid >> 5;
    const int rA = (w & 3) * 32;
    const int nbase = (w >> 2) * 32;

    float acc[2][4][4];
    #pragma unroll
    for (int mi = 0; mi < 2; mi++)
        #pragma unroll
        for (int ni = 0; ni < 4; ni++)
            #pragma unroll
            for (int j = 0; j < 4; j++) acc[mi][ni][j] = 0.f;

    for (int ch = 0; ch < 2; ch++) {
        const int kc = ch * 32;
        __syncthreads();
        #pragma unroll
        for (int it = 0; it < 16; it++) {
            int idx = it * 256 + tid;
            int kk = idx & 31, r = idx >> 5;
            int gk = kc + kk;
            float v = (gk < HW) ? A[(size_t)(r0 + r) * HW + gk] : 0.f;
            split2(v, sA[0][r][kk], sA[1][r][kk]);
        }
        #pragma unroll
        for (int it = 0; it < 8; it++) {
            int idx = it * 256 + tid;
            int n = idx & 63, kk = idx >> 6;
            int gk = kc + kk;
            float v = (gk < HW && n < S2) ? d_P[gk * S2 + n] : 0.f;
            split2(v, sB[0][n][kk], sB[1][n][kk]);
        }
        __syncthreads();
        #pragma unroll
        for (int kk = 0; kk < 32; kk += 16) {
            uint32_t aH[2][4], aL[2][4];
            const int arow = rA + (lane & 7) + ((lane >> 3) & 1) * 8;
            const int akc  = kk + (lane >> 4) * 8;
            #pragma unroll
            for (int mi = 0; mi < 2; mi++) {
                ldsm4(smem_u32(&sA[0][arow + mi * 16][akc]), aH[mi]);
                ldsm4(smem_u32(&sA[1][arow + mi * 16][akc]), aL[mi]);
            }
            #pragma unroll
            for (int np = 0; np < 2; np++) {
                uint32_t bH[4], bL[4];
                const int brow = nbase + np * 16 + (lane >> 4) * 8 + (lane & 7);
                const int bkc  = kk + ((lane >> 3) & 1) * 8;
                ldsm4(smem_u32(&sB[0][brow][bkc]), bH);
                ldsm4(smem_u32(&sB[1][brow][bkc]), bL);
                #pragma unroll
                for (int mi = 0; mi < 2; mi++) {
                    #pragma unroll
                    for (int h = 0; h < 2; h++) {
                        int ni = 2 * np + h;
                        mma16816(acc[mi][ni], aH[mi], &bH[2 * h]);
                        mma16816(acc[mi][ni], aH[mi], &bL[2 * h]);
                        mma16816(acc[mi][ni], aL[mi], &bH[2 * h]);
                    }
                }
            }
        }
    }

    __syncthreads();
    bf16 (*sH)[128] = reinterpret_cast<bf16(*)[128]>(smr);          // [49][128]
    bf16 (*sL)[128] = reinterpret_cast<bf16(*)[128]>(smr + 12800);
    const int g2 = lane >> 2, tg = lane & 3;
    #pragma unroll
    for (int mi = 0; mi < 2; mi++) {
        #pragma unroll
        for (int ni = 0; ni < 4; ni++) {
            int rowl = rA + mi * 16 + g2;
            int col = nbase + ni * 8 + tg * 2;
            #pragma unroll
            for (int j = 0; j < 4; j++) {
                int rr = rowl + (j >> 1) * 8;
                int nn = col + (j & 1);
                if (nn < S2) {
                    bf16 h, l;
                    split2(acc[mi][ni][j], h, l);
                    sH[nn][rr] = h;
                    sL[nn][rr] = l;
                }
            }
        }
    }
    __syncthreads();
    for (int idx = tid; idx < S2 * 128; idx += 256) {
        int i = idx >> 7, r = idx & 127;
        size_t o = (size_t)i * BC + r0 + r;
        Ch[o] = sH[i][r];
        Cl[o] = sL[i][r];
    }
}

// ---------------------------------------------------------------------------
// Engine B (pre-split bf16 planes, cp.async double-buffered) — stageD/5/6.
// Runtime npMax (uniform per CTA); general split-K divisor; per-sub k clamp.
// ---------------------------------------------------------------------------
template<bool RELU, bool PACKOUT, bool LSEL>
__global__ void __launch_bounds__(256, 2) mmag_p(
    const bf16* __restrict__ Ah, const bf16* __restrict__ Al,
    const bf16* __restrict__ Bh, const bf16* __restrict__ Bl,
    float* __restrict__ C, bf16* __restrict__ Ch, bf16* __restrict__ Cl,
    int lda, int ldb, int ldc, int Nreal, int npMaxIn,
    int kchunks, int kstride, int zdivisor, int kmax,
    size_t astride, size_t bstride, size_t cstride, size_t cstride2)
{
    extern __shared__ bf16 S[];   // sA[2buf][2pl][128][40] then sB same: 81920 B
    const int tid = threadIdx.x;
    const int z = blockIdx.z;
    const int batch = z / zdivisor;
    const int sub = z - batch * zdivisor;
    const bf16* Aph = Ah + (size_t)batch * astride;
    const bf16* Apl = Al + (size_t)batch * astride;
    const size_t boff = (LSEL ? (size_t)c_l_of_i[batch] : (size_t)batch) * bstride;
    const bf16* Bph = Bh + boff;
    const bf16* Bpl = Bl + boff;
    float* Cp = C + (size_t)batch * cstride + (size_t)sub * cstride2;
    const int kbeg = sub * kstride;
    const int nch = min(kchunks, (kmax - kbeg + 31) >> 5);
    const int r0 = blockIdx.y * 128;
    const int n0 = blockIdx.x * 128;
    const int lane = tid & 31, w = tid >> 5;
    const int rA = (w & 3) * 32;
    const int nbase = (w >> 2) * 64;
    const uint32_t sbase = smem_u32(S);
    constexpr uint32_t SBOFF = 2 * 2 * 128 * 40 * 2;   // bytes

    int npMax = npMaxIn;
    if (LSEL) {
        int d = 2 * c_l_of_i[batch] + 1;
        npMax = (8 * d + 31) >> 5;        // 1..4
    }

    float acc[2][8][4];
    #pragma unroll
    for (int mi = 0; mi < 2; mi++)
        #pragma unroll
        for (int ni = 0; ni < 8; ni++)
            #pragma unroll
            for (int j = 0; j < 4; j++) acc[mi][ni][j] = 0.f;

    auto copyin = [&](int buf, int kc) {
        #pragma unroll
        for (int it = 0; it < 8; it++) {
            int idx = it * 256 + tid;
            int q = idx & 7, r = (idx >> 3) & 127, p = idx >> 10;
            const bf16* g = (p ? Apl : Aph) + (size_t)(r0 + r) * lda + kc + q * 4;
            uint32_t d = sbase + (((buf * 2 + p) * 128 + r) * 40 + q * 4) * 2;
            asm volatile("cp.async.ca.shared.global [%0], [%1], 8;"
                         :: "r"(d), "l"(g));
        }
        for (int p = 0; p < 2; p++) {
            for (int itn = 0; itn < npMax; itn++) {
                int q = tid & 7, r = itn * 32 + (tid >> 3);
                const bf16* g = (p ? Bpl : Bph) + (size_t)(n0 + r) * ldb + kc + q * 4;
                uint32_t d = sbase + SBOFF + (((buf * 2 + p) * 128 + r) * 40 + q * 4) * 2;
                asm volatile("cp.async.ca.shared.global [%0], [%1], 8;"
                             :: "r"(d), "l"(g));
            }
        }
        asm volatile("cp.async.commit_group;" ::: "memory");
    };

    int buf = 0;
    copyin(0, kbeg);

    for (int ch = 0; ch < nch; ch++) {
        if (ch + 1 < nch) {
            copyin(buf ^ 1, kbeg + (ch + 1) * 32);
            asm volatile("cp.async.wait_group 1;" ::: "memory");
        } else {
            asm volatile("cp.async.wait_group 0;" ::: "memory");
        }
        __syncthreads();

        #pragma unroll
        for (int kk = 0; kk < 32; kk += 16) {
            uint32_t aH[2][4], aL[2][4];
            const int arow = rA + (lane & 7) + ((lane >> 3) & 1) * 8;
            const int akc  = kk + (lane >> 4) * 8;
            #pragma unroll
            for (int mi = 0; mi < 2; mi++) {
                uint32_t a0 = sbase + (((buf * 2 + 0) * 128 + arow + mi * 16) * 40 + akc) * 2;
                uint32_t a1 = sbase + (((buf * 2 + 1) * 128 + arow + mi * 16) * 40 + akc) * 2;
                ldsm4(a0, aH[mi]);
                ldsm4(a1, aL[mi]);
            }
            #pragma unroll
            for (int np = 0; np < 4; np++) {
                if ((nbase >> 4) + np < (npMax << 1)) {
                    uint32_t bH[4], bL[4];
                    const int brow = nbase + np * 16 + (lane >> 4) * 8 + (lane & 7);
                    const int bkc  = kk + ((lane >> 3) & 1) * 8;
                    uint32_t b0 = sbase + SBOFF + (((buf * 2 + 0) * 128 + brow) * 40 + bkc) * 2;
                    uint32_t b1 = sbase + SBOFF + (((buf * 2 + 1) * 128 + brow) * 40 + bkc) * 2;
                    ldsm4(b0, bH);
                    ldsm4(b1, bL);
                    #pragma unroll
                    for (int mi = 0; mi < 2; mi++) {
                        #pragma unroll
                        for (int h = 0; h < 2; h++) {
                            int ni = 2 * np + h;
                            mma16816(acc[mi][ni], aH[mi], &bH[2 * h]);
                            mma16816(acc[mi][ni], aH[mi], &bL[2 * h]);
                            mma16816(acc[mi][ni], aL[mi], &bH[2 * h]);
                        }
                    }
                }
            }
        }
        __syncthreads();
        buf ^= 1;
    }

    const int g2 = lane >> 2, tg = lane & 3;
    #pragma unroll
    for (int mi = 0; mi < 2; mi++) {
        #pragma unroll
        for (int ni = 0; ni < 8; ni++) {
            if (((nbase + ni * 8) >> 5) >= npMax) continue;
            int row = r0 + rA + mi * 16 + g2;
            int col = n0 + nbase + ni * 8 + tg * 2;
            float v[4];
            #pragma unroll
            for (int j = 0; j < 4; j++) {
                v[j] = acc[mi][ni][j];
                if (RELU) v[j] = fmaxf(v[j], 0.f);
            }
            if (PACKOUT) {
                #pragma unroll
                for (int h = 0; h < 2; h++) {
                    int rr = row + h * 8;
                    bf16 h0, l0, h1, l1;
                    split2(v[2 * h + 0], h0, l0);
                    split2(v[2 * h + 1], h1, l1);
                    *(uint32_t*)&Ch[(size_t)rr * ldc + col] = pack2(h0, h1);
                    *(uint32_t*)&Cl[(size_t)rr * ldc + col] = pack2(l0, l1);
                }
            } else {
                #pragma unroll
                for (int j = 0; j < 4; j++) {
                    int rr = row + (j >> 1) * 8;
                    int nn = col + (j & 1);
                    if (nn < Nreal) Cp[(size_t)rr * ldc + nn] = v[j];
                }
            }
        }
    }
}

// ---------------------------------------------------------------------------
// Small kernels
// ---------------------------------------------------------------------------
__global__ void k_Pq(const float* __restrict__ proj_w, const float* __restrict__ proj_Y) {
    const int tid = threadIdx.x;
    for (int t = tid; t < HW * S2; t += 256) {
        int hw = t / S2, i = t % S2;
        const float* wr = proj_w + hw * NP;
        float acc = 0.f;
        #pragma unroll 8
        for (int n = 0; n < NP; n++) acc += wr[n] * proj_Y[n * S2 + i];
        d_P[t] = acc * RS192;
    }
    __syncthreads();
    if (tid < S2) {
        float a = 0.f;
        for (int hw = 0; hw < HW; hw++) a += d_P[hw * S2 + tid];
        d_q[tid] = a;
    }
}

__global__ void k_bpsi(const float* __restrict__ conv_b) {
    __shared__ float part[8][33];
    const int lane = threadIdx.x & 31, w = threadIdx.x >> 5;
    const int t = blockIdx.x * 32 + lane;
    float acc = 0.f;
    if (t < GI) {
        #pragma unroll 8
        for (int ff = 0; ff < 64; ff++) {
            int f = w * 64 + ff;
            acc += conv_b[f] * d_psi[f * GI + t];
        }
    }
    part[w][lane] = acc;
    __syncthreads();
    if (w == 0 && t < GI) {
        float s = 0.f;
        #pragma unroll
        for (int j = 0; j < 8; j++) s += part[j][lane];
        d_bpsi[t] = s * RS512;
    }
}

__global__ void k_psi2(const float* __restrict__ so3_w, const float* __restrict__ so3_D) {
    int w = (blockIdx.x * blockDim.x + threadIdx.x) >> 5;
    int lane = threadIdx.x & 31;
    if (w >= G_ * SO3) return;
    int f = w / SO3, i = w % SO3;
    float acc = 0.f;
    for (int n = lane; n < NP; n += 32) acc += so3_w[f * NP + n] * so3_D[n * SO3 + i];
    #pragma unroll
    for (int o = 16; o; o >>= 1) acc += __shfl_xor_sync(0xFFFFFFFFu, acc, o);
    if (lane == 0) d_psi2[w] = acc * RS192;
}

__global__ void k_tpose(const float* __restrict__ in, bf16* __restrict__ oh,
                        bf16* __restrict__ ol, int inR, int inC, int ldo) {
    __shared__ float tl[32][33];
    int n0 = blockIdx.x * 32, k0 = blockIdx.y * 32;
    #pragma unroll
    for (int j = 0; j < 4; j++) {
        int k = k0 + threadIdx.y + j * 8, n = n0 + threadIdx.x;
        tl[threadIdx.y + j * 8][threadIdx.x] =
            (k < inR && n < inC) ? in[(size_t)k * inC + n] : 0.f;
    }
    __syncthreads();
    #pragma unroll
    for (int j = 0; j < 4; j++) {
        int n = n0 + threadIdx.y + j * 8, k = k0 + threadIdx.x;
        bf16 h, l;
        split2(tl[threadIdx.x][threadIdx.y + j * 8], h, l);
        oh[(size_t)n * ldo + k] = h;
        ol[(size_t)n * ldo + k] = l;
    }
}

// partD (6 k-slabs) + bias -> x4 planes [1024][512]
__global__ void k_x4() {
    int t = blockIdx.x * blockDim.x + threadIdx.x;
    if (t >= 1024 * 512) return;
    int row = t >> 9, col = t & 511;
    int b = row >> 3, g = row & 7;
    float v = 0.f;
    if (col < SO3) {
        int l = 6;
        while (col < c_off2[l]) l--;
        int d = 2 * l + 1, r = col - c_off2[l];
        int u = r / d, m = r - u * d, i = l * l + m;
        size_t o = (size_t)i * 128 * 104 + (size_t)b * 104 + g * d + u;
        float s = 0.f;
        #pragma unroll
        for (int zz = 0; zz < 6; zz++)
            s += d_partD[o + (size_t)zz * 49 * 128 * 104];
        v = s + d_bpsi[g * S2 + l * l + u] * d_q[l * l + m];
    }
    bf16 h, lo;
    split2(v, h, lo);
    d_x4h[t] = h;
    d_x4l[t] = lo;
}

__global__ void k_red6() {
    int t = blockIdx.x * blockDim.x + threadIdx.x;
    if (t >= 1024 * SO3) return;
    int row = t / SO3, col = t - row * SO3;
    float s = 0.f;
    #pragma unroll
    for (int zz = 0; zz < 8; zz++)
        s += d_part6[(size_t)zz * 1024 * 512 + (size_t)row * 512 + col];
    d_x5[t] = s;
}

__global__ void stageH_kernel(float* __restrict__ out) {
    int t = blockIdx.x * blockDim.x + threadIdx.x;
    if (t >= B_ * SO3) return;
    int b = t / SO3, j = t - b * SO3;
    int l = 6;
    while (j < c_off2[l]) l--;
    int d = 2 * l + 1;
    int r = j - c_off2[l];
    int v = r / d, m = r - v * d;
    float acc = 0.f;
    #pragma unroll
    for (int f = 0; f < G_; f++) {
        const float* xr = d_x5 + (size_t)(b * G_ + f) * SO3 + c_off2[l];
        const float* pr = d_psi2 + f * SO3 + c_off2[l];
        for (int u = 0; u < d; u++) acc += xr[u * d + m] * pr[u * d + v];
    }
    out[t] = acc * (1.0f / sqrtf(8.0f * d));
}

// ---------------------------------------------------------------------------
// Host launcher — multi-stream fork/join (capture-legal via events)
// ---------------------------------------------------------------------------
extern "C" void kernel_launch(void* const* d_in, const int* in_sizes, int n_in,
                              void* d_out, int out_size) {
    const float* fmap     = (const float*)d_in[0];
    const float* conv_w   = (const float*)d_in[1];
    const float* conv_b   = (const float*)d_in[2];
    const float* proj_w   = (const float*)d_in[3];
    const float* proj_Y   = (const float*)d_in[4];
    const float* fs_w     = (const float*)d_in[5];
    const float* fs_Y     = (const float*)d_in[6];
    const float* act_to   = (const float*)d_in[7];
    const float* act_from = (const float*)d_in[8];
    const float* so3_w    = (const float*)d_in[9];
    const float* so3_D    = (const float*)d_in[10];
    float* out = (float*)d_out;

    float *pPsi, *pPartD, *pPart6;
    bf16 *pADh, *pADl, *pW2th, *pW2tl, *pX4h, *pX4l, *pB5h, *pB5l;
    bf16 *pGh, *pGl, *pB6h, *pB6l;
    cudaGetSymbolAddress((void**)&pPsi,   d_psi);
    cudaGetSymbolAddress((void**)&pPartD, d_partD);
    cudaGetSymbolAddress((void**)&pPart6, d_part6);
    cudaGetSymbolAddress((void**)&pADh,   d_ADh);
    cudaGetSymbolAddress((void**)&pADl,   d_ADl);
    cudaGetSymbolAddress((void**)&pW2th,  d_W2th);
    cudaGetSymbolAddress((void**)&pW2tl,  d_W2tl);
    cudaGetSymbolAddress((void**)&pX4h,   d_x4h);
    cudaGetSymbolAddress((void**)&pX4l,   d_x4l);
    cudaGetSymbolAddress((void**)&pB5h,   d_bt5h);
    cudaGetSymbolAddress((void**)&pB5l,   d_bt5l);
    cudaGetSymbolAddress((void**)&pGh,    d_gacth);
    cudaGetSymbolAddress((void**)&pGl,    d_gactl);
    cudaGetSymbolAddress((void**)&pB6h,   d_bt6h);
    cudaGetSymbolAddress((void**)&pB6l,   d_bt6l);

    auto* kPsi = mmag_f<false, true, 64, 0>;
    auto* kW2  = mmag_f<true,  true, 64, 1>;
    auto* kSD = mmag_p<false, false, true >;
    auto* kS5 = mmag_p<true,  true,  false>;
    auto* kS6 = mmag_p<false, false, false>;
    constexpr int SMP = 2 * 2 * 2 * 128 * 40 * 2;   // 81920 B
    cudaFuncSetAttribute(kSD, cudaFuncAttributeMaxDynamicSharedMemorySize, SMP);
    cudaFuncSetAttribute(kS5, cudaFuncAttributeMaxDynamicSharedMemorySize, SMP);
    cudaFuncSetAttribute(kS6, cudaFuncAttributeMaxDynamicSharedMemorySize, SMP);

    // one-time host-side infra (no device memory, identical GPU work per call)
    static cudaStream_t s1 = nullptr, s2 = nullptr;
    static cudaEvent_t evRoot = nullptr, evW2 = nullptr, evBps = nullptr, evAux = nullptr;
    if (s1 == nullptr) {
        cudaStreamCreateWithFlags(&s1, cudaStreamNonBlocking);
        cudaStreamCreateWithFlags(&s2, cudaStreamNonBlocking);
        cudaEventCreateWithFlags(&evRoot, cudaEventDisableTiming);
        cudaEventCreateWithFlags(&evW2,   cudaEventDisableTiming);
        cudaEventCreateWithFlags(&evBps,  cudaEventDisableTiming);
        cudaEventCreateWithFlags(&evAux,  cudaEventDisableTiming);
    }

    // fork: s1 (W2 chain), s2 (operand preps) join the capture via evRoot
    cudaEventRecord(evRoot, 0);
    cudaStreamWaitEvent(s1, evRoot, 0);
    cudaStreamWaitEvent(s2, evRoot, 0);

    // main chain (submission order chosen so kSD is the 6th kernel for ncu)
    k_Pq<<<1, 256>>>(proj_w, proj_Y);                                    // 1
    kAD_kernel<<<2048, 256>>>(fmap, pADh, pADl);                         // 2

    // s1: psi -> W2t (direct permuted store) -> bpsi
    kPsi<<<dim3(1, 32, 1), 256, 0, s1>>>(fs_w, fs_Y, pPsi,
                                         NP, S2, S2, NP, S2, RS192, 6);  // 3
    kW2<<<dim3(7, 16, 1), 256, 0, s1>>>(conv_w, pPsi, (float*)0,
                                        C_, GI, 0, FIN, GI, RS512, 16);  // 4
    cudaEventRecord(evW2, s1);
    k_bpsi<<<(GI + 31) / 32, 256, 0, s1>>>(conv_b);                      // 5
    cudaEventRecord(evBps, s1);

    cudaStreamWaitEvent(0, evW2, 0);
    // stageD: 49 batches (M=128, N=8d, K=2048), split-K x6 -> 294 CTAs (1 wave)
    kSD<<<dim3(1, 1, 294), 256, SMP>>>(pADh, pADl, pW2th, pW2tl,         // 6
        pPartD, (bf16*)0, (bf16*)0,
        C_, C_, 104, 104, 4, 11, 352, 6, C_,
        BC, (size_t)128 * C_, (size_t)128 * 104, (size_t)49 * 128 * 104);

    // s2: operand preps (graph DAG: run concurrently with kAD/kSD)
    k_psi2<<<(G_ * SO3 * 32 + 127) / 128, 128, 0, s2>>>(so3_w, so3_D);
    k_tpose<<<dim3(128, 15), dim3(32, 8), 0, s2>>>(act_to,   pB5h, pB5l, SO3, NG, 480);
    k_tpose<<<dim3(16, 128), dim3(32, 8), 0, s2>>>(act_from, pB6h, pB6l, NG, SO3, 4096);
    cudaEventRecord(evAux, s2);

    cudaStreamWaitEvent(0, evBps, 0);
    k_x4<<<(1024 * 512 + 255) / 256, 256>>>();

    cudaStreamWaitEvent(0, evAux, 0);
    // stage5: gact planes = relu(x4 @ act_to)  (M=1024, N=4096, K=480)
    kS5<<<dim3(32, 8, 1), 256, SMP>>>(pX4h, pX4l, pB5h, pB5l,
        (float*)0, pGh, pGl,
        512, 480, 4096, 4096, 4, 15, 480, 1, 480, 0, 0, 0, 0);

    // stage6: part6[z] = gact @ act_from  (M=1024, N=512, K=4096), split-K x8
    kS6<<<dim3(4, 8, 8), 256, SMP>>>(pGh, pGl, pB6h, pB6l,
        pPart6, (bf16*)0, (bf16*)0,
        4096, 4096, 512, 512, 4, 16, 512, 8, 4096,
        0, 0, 0, (size_t)1024 * 512);
    k_red6<<<(1024 * SO3 + 255) / 256, 256>>>();

    stageH_kernel<<<(B_ * SO3 + 255) / 256, 256>>>(out);
}